// round 12
// baseline (speedup 1.0000x reference)
#include <cuda_runtime.h>
#include <cuda_bf16.h>
#include <math.h>
#include <stdint.h>

// Problem constants
#define BATCH 2
#define SEQ   2048
#define DIM   1024
#define NHEAD 16
#define HDIM  64
#define MROWS (BATCH*SEQ)   // 4096

// Scratch buffers (allocation-free rule: static device globals)
__device__ float    g_q[MROWS * DIM];
__device__ float    g_k[MROWS * DIM];
__device__ float    g_v[MROWS * DIM];
__device__ uint32_t g_qp[MROWS * DIM];      // tf32 packed Q [b][h][s][hdperm]
__device__ uint32_t g_kp[MROWS * DIM];      // tf32 packed K [b][h][sperm][hdperm]
__device__ uint32_t g_vt[MROWS * DIM];      // tf32 packed V [b][h][hd][keyperm]
__device__ uint32_t g_xp[MROWS * DIM];      // tf32 packed X (k-perm)
__device__ uint32_t g_wp[4 * DIM * DIM];    // tf32 packed Wq,Wk,Wv,Wo (k-perm)
__device__ uint32_t g_ap[MROWS * DIM];      // tf32 packed attn-out (k-perm)

__device__ __forceinline__ uint32_t f2tf32(float f) {
    uint32_t u;
    asm("cvt.rna.tf32.f32 %0, %1;" : "=r"(u) : "f"(f));
    return u;
}

__device__ __forceinline__ float ex2(float x) {
    float y;
    asm("ex2.approx.f32 %0, %1;" : "=f"(y) : "f"(x));
    return y;
}

__device__ __forceinline__ void mma_tf32(float* d, const uint32_t* a,
                                         const uint32_t* b, const float* c) {
    asm volatile(
        "mma.sync.aligned.m16n8k8.row.col.f32.tf32.tf32.f32 "
        "{%0,%1,%2,%3}, {%4,%5,%6,%7}, {%8,%9}, {%10,%11,%12,%13};\n"
        : "=f"(d[0]), "=f"(d[1]), "=f"(d[2]), "=f"(d[3])
        : "r"(a[0]), "r"(a[1]), "r"(a[2]), "r"(a[3]),
          "r"(b[0]), "r"(b[1]),
          "f"(c[0]), "f"(c[1]), "f"(c[2]), "f"(c[3]));
}

__device__ __forceinline__ void cp_async16(uint32_t sm_addr, const void* gptr) {
    asm volatile("cp.async.cg.shared.global [%0], [%1], 16;\n"
                 :: "r"(sm_addr), "l"(gptr));
}
__device__ __forceinline__ void cp_commit() {
    asm volatile("cp.async.commit_group;\n" ::: "memory");
}

// perm within groups of 8: logical l -> 2*(l%4) + (l/4)
__device__ __forceinline__ int perm8(int l) {
    return (l & ~7) | (2 * (l & 3)) | ((l >> 2) & 1);
}

// ---------------------------------------------------------------------------
// Pack fp32 [rows][1024] -> tf32 with perm8 on the k axis. 256 thr, 2 rows/blk.
// ---------------------------------------------------------------------------
__global__ __launch_bounds__(256) void pack_tf32_kernel(
    const float* __restrict__ in, uint32_t* __restrict__ out)
{
    const int t = threadIdx.x;
    const size_t base = ((size_t)blockIdx.x * 2 + (t >> 7)) * DIM + (t & 127) * 8;
    const float4 v0 = *(const float4*)(in + base);
    const float4 v1 = *(const float4*)(in + base + 4);
    uint4 o0, o1;
    o0.x = f2tf32(v0.x); o0.y = f2tf32(v1.x);
    o0.z = f2tf32(v0.y); o0.w = f2tf32(v1.y);
    o1.x = f2tf32(v0.z); o1.y = f2tf32(v1.z);
    o1.z = f2tf32(v0.w); o1.w = f2tf32(v1.w);
    *(uint4*)(out + base)     = o0;
    *(uint4*)(out + base + 4) = o1;
}

// Fused pack of the 4 weight matrices: grid (DIM/2, 4)
__global__ __launch_bounds__(256) void pack_w4_kernel(
    const float* __restrict__ Wq, const float* __restrict__ Wk,
    const float* __restrict__ Wv, const float* __restrict__ Wo,
    uint32_t* __restrict__ out)
{
    const float* W;
    switch (blockIdx.y) {
        case 0: W = Wq; break;
        case 1: W = Wk; break;
        case 2: W = Wv; break;
        default: W = Wo; break;
    }
    uint32_t* o = out + (size_t)blockIdx.y * DIM * DIM;
    const int t = threadIdx.x;
    const size_t base = ((size_t)blockIdx.x * 2 + (t >> 7)) * DIM + (t & 127) * 8;
    const float4 v0 = *(const float4*)(W + base);
    const float4 v1 = *(const float4*)(W + base + 4);
    uint4 o0, o1;
    o0.x = f2tf32(v0.x); o0.y = f2tf32(v1.x);
    o0.z = f2tf32(v0.y); o0.w = f2tf32(v1.y);
    o1.x = f2tf32(v0.z); o1.y = f2tf32(v1.z);
    o1.z = f2tf32(v0.w); o1.w = f2tf32(v1.w);
    *(uint4*)(o + base)     = o0;
    *(uint4*)(o + base + 4) = o1;
}

// ---------------------------------------------------------------------------
// Packed tf32 GEMM, 2-stage cp.async, ONE barrier per k-tile, 2 blocks/SM.
// (unchanged — measured equal-best; GEMM theory family exhausted R7/R8/R10)
// ---------------------------------------------------------------------------
#define GSTR 40
#define NKT  (DIM / 32)   // 32 k-tiles

__device__ __forceinline__ void gemm_pk_body(
    const uint32_t* __restrict__ A, const uint32_t* __restrict__ W,
    const float* __restrict__ bias, float* __restrict__ C,
    int bx, int by, uint32_t* gsm)
{
    const int tid  = threadIdx.x;
    const int bm   = by * 128;
    const int bn   = bx * 128;
    const int warp = tid >> 5;
    const int lane = tid & 31;
    const int wm   = (warp >> 2) * 64;
    const int wn   = (warp & 3) * 32;
    const int gr   = lane >> 2;
    const int tg   = lane & 3;

    const uint32_t sm_a = (uint32_t)__cvta_generic_to_shared(gsm);

    const int lr = tid >> 1;
    const int lc = (tid & 1) * 16;

    float acc[4][4][4];
#pragma unroll
    for (int i = 0; i < 4; i++)
#pragma unroll
        for (int j = 0; j < 4; j++)
#pragma unroll
            for (int c = 0; c < 4; c++) acc[i][j][c] = 0.f;

    const uint32_t* arow = A + (size_t)(bm + lr) * DIM + lc;
    const uint32_t* wrow = W + (size_t)(bn + lr) * DIM + lc;

    auto issue = [&](int t) {
        const int st = t & 1;
        const uint32_t abase = sm_a + ((st * 256 + lr) * GSTR + lc) * 4;
        const uint32_t bbase = abase + 128 * GSTR * 4;
        const uint32_t* ag = arow + t * 32;
        const uint32_t* wg = wrow + t * 32;
        cp_async16(abase,      ag);
        cp_async16(abase + 16, ag + 4);
        cp_async16(abase + 32, ag + 8);
        cp_async16(abase + 48, ag + 12);
        cp_async16(bbase,      wg);
        cp_async16(bbase + 16, wg + 4);
        cp_async16(bbase + 32, wg + 8);
        cp_async16(bbase + 48, wg + 12);
        cp_commit();
    };

    issue(0);

    for (int t = 0; t < NKT; t++) {
        asm volatile("cp.async.wait_group 0;\n" ::: "memory");
        __syncthreads();
        if (t + 1 < NKT) issue(t + 1);

        const uint32_t* Ab = gsm + (t & 1) * 256 * GSTR;
        const uint32_t* Bb = Ab + 128 * GSTR;

#pragma unroll
        for (int ks = 0; ks < 4; ks++) {
            const int kk = ks * 8;
            uint32_t af[4][4], bf[4][2];
#pragma unroll
            for (int i = 0; i < 4; i++) {
                const int r = wm + i * 16 + gr;
                const uint2 a02 = *(const uint2*)&Ab[r * GSTR + kk + 2 * tg];
                const uint2 a13 = *(const uint2*)&Ab[(r + 8) * GSTR + kk + 2 * tg];
                af[i][0] = a02.x; af[i][1] = a13.x;
                af[i][2] = a02.y; af[i][3] = a13.y;
            }
#pragma unroll
            for (int j = 0; j < 4; j++) {
                const int n = wn + j * 8 + gr;
                const uint2 bb = *(const uint2*)&Bb[n * GSTR + kk + 2 * tg];
                bf[j][0] = bb.x; bf[j][1] = bb.y;
            }
#pragma unroll
            for (int i = 0; i < 4; i++)
#pragma unroll
                for (int j = 0; j < 4; j++)
                    mma_tf32(acc[i][j], af[i], bf[j], acc[i][j]);
        }
    }

#pragma unroll
    for (int i = 0; i < 4; i++) {
#pragma unroll
        for (int j = 0; j < 4; j++) {
            const int row = bm + wm + i * 16 + gr;
            const int col = bn + wn + j * 8 + 2 * tg;
            const float2 b01 = *(const float2*)(bias + col);
            float2 o0, o1;
            o0.x = acc[i][j][0] + b01.x;
            o0.y = acc[i][j][1] + b01.y;
            o1.x = acc[i][j][2] + b01.x;
            o1.y = acc[i][j][3] + b01.y;
            *(float2*)(C + (size_t)row * DIM + col)       = o0;
            *(float2*)(C + (size_t)(row + 8) * DIM + col) = o1;
        }
    }
}

__global__ __launch_bounds__(256, 2) void gemm_pk_kernel(
    const uint32_t* __restrict__ A, const uint32_t* __restrict__ W,
    const float* __restrict__ bias, float* __restrict__ C)
{
    extern __shared__ uint32_t gsm[];
    gemm_pk_body(A, W, bias, C, blockIdx.x, blockIdx.y, gsm);
}

__global__ __launch_bounds__(256, 2) void gemm_pk_qkv_kernel(
    const uint32_t* __restrict__ A, const uint32_t* __restrict__ Wp,
    const float* __restrict__ bq, const float* __restrict__ bk,
    const float* __restrict__ bv,
    float* __restrict__ Cq, float* __restrict__ Ck, float* __restrict__ Cv)
{
    extern __shared__ uint32_t gsm[];
    const float* b; float* C;
    if (blockIdx.z == 0)      { b = bq; C = Cq; }
    else if (blockIdx.z == 1) { b = bk; C = Ck; }
    else                      { b = bv; C = Cv; }
    gemm_pk_body(A, Wp + (size_t)blockIdx.z * DIM * DIM, b, C,
                 blockIdx.x, blockIdx.y, gsm);
}

// ---------------------------------------------------------------------------
// Prepack Q/K v2: fused RMSNorm + tf32 + head split + perm, vectorized stores.
// ---------------------------------------------------------------------------
__global__ __launch_bounds__(128) void prepack_qk_kernel(
    const float* __restrict__ qin, const float* __restrict__ kin,
    const float* __restrict__ nqw, const float* __restrict__ nkw,
    uint32_t* __restrict__ qp, uint32_t* __restrict__ kp)
{
    const int row = blockIdx.x;
    const int isk = blockIdx.y;
    const float* src = (isk ? kin : qin) + (size_t)row * DIM;
    const float* w   = isk ? nkw : nqw;
    uint32_t* dstbuf = isk ? kp : qp;
    const int t = threadIdx.x;

    const float4 v0 = *(const float4*)(src + t * 8);
    const float4 v1 = *(const float4*)(src + t * 8 + 4);
    float ss = v0.x * v0.x + v0.y * v0.y + v0.z * v0.z + v0.w * v0.w
             + v1.x * v1.x + v1.y * v1.y + v1.z * v1.z + v1.w * v1.w;
#pragma unroll
    for (int off = 16; off > 0; off >>= 1)
        ss += __shfl_xor_sync(0xFFFFFFFFu, ss, off);
    __shared__ float red[4];
    if ((t & 31) == 0) red[t >> 5] = ss;
    __syncthreads();
    const float total = red[0] + red[1] + red[2] + red[3];

    const float SCALE = 0.125f * 1.4426950408889634f;
    float norm = rsqrtf(total * (1.0f / DIM) + 1e-6f);
    if (!isk) norm *= SCALE;

    const int b = row >> 11;
    const int s = row & 2047;
    const int srow = isk ? perm8(s) : s;
    const int h = t >> 3;
    const float4 w0 = *(const float4*)(w + t * 8);
    const float4 w1 = *(const float4*)(w + t * 8 + 4);

    const float y0 = v0.x * norm * w0.x, y1 = v0.y * norm * w0.y;
    const float y2 = v0.z * norm * w0.z, y3 = v0.w * norm * w0.w;
    const float y4 = v1.x * norm * w1.x, y5 = v1.y * norm * w1.y;
    const float y6 = v1.z * norm * w1.z, y7 = v1.w * norm * w1.w;

    uint32_t* dst = dstbuf + (((size_t)b * NHEAD + h) * SEQ + srow) * 64
                  + (t & 7) * 8;
    uint4 o0, o1;
    o0.x = f2tf32(y0); o0.y = f2tf32(y4);
    o0.z = f2tf32(y1); o0.w = f2tf32(y5);
    o1.x = f2tf32(y2); o1.y = f2tf32(y6);
    o1.z = f2tf32(y3); o1.w = f2tf32(y7);
    *(uint4*)(dst)     = o0;
    *(uint4*)(dst + 4) = o1;
}

// ---------------------------------------------------------------------------
// Prepack V: transpose to [b][h][hd][key-perm], tf32.
// ---------------------------------------------------------------------------
__global__ __launch_bounds__(256) void prepack_v_kernel(
    const float* __restrict__ vin, uint32_t* __restrict__ vt)
{
    __shared__ float ts[64][65];
    const int t  = threadIdx.x;
    const int k0 = blockIdx.x * 64;
    const int h  = blockIdx.y;
    const int b  = blockIdx.z;

    for (int i = t; i < 64 * 16; i += 256) {
        const int r  = i >> 4;
        const int c4 = i & 15;
        const float4 vv = *(const float4*)(
            vin + ((size_t)b * SEQ + k0 + r) * DIM + h * HDIM + c4 * 4);
        ts[r][c4 * 4 + 0] = vv.x;
        ts[r][c4 * 4 + 1] = vv.y;
        ts[r][c4 * 4 + 2] = vv.z;
        ts[r][c4 * 4 + 3] = vv.w;
    }
    __syncthreads();

    const int hd = t >> 2;
    uint32_t* dst = vt + (((size_t)b * NHEAD + h) * 64 + hd) * SEQ + k0;
#pragma unroll
    for (int g2 = 0; g2 < 2; g2++) {
        const int g = (t & 3) * 2 + g2;
        uint4 w0, w1;
        w0.x = f2tf32(ts[g * 8 + 0][hd]); w0.y = f2tf32(ts[g * 8 + 4][hd]);
        w0.z = f2tf32(ts[g * 8 + 1][hd]); w0.w = f2tf32(ts[g * 8 + 5][hd]);
        w1.x = f2tf32(ts[g * 8 + 2][hd]); w1.y = f2tf32(ts[g * 8 + 6][hd]);
        w1.z = f2tf32(ts[g * 8 + 3][hd]); w1.w = f2tf32(ts[g * 8 + 7][hd]);
        *(uint4*)(dst + g * 8)     = w0;
        *(uint4*)(dst + g * 8 + 4) = w1;
    }
}

// ---------------------------------------------------------------------------
// Tensor-core flash attention v6: 2 m-tiles per warp (32 Q rows/warp, 128 Q
// rows/block). Each K/V fragment load feeds TWO MMAs -> per-FLOP smem reads
// -44%, K/V gmem traffic per FLOP halved. Static-max softmax (R11), split-
// commit K/V (R9), hoisted cp.async addressing (R11). 3 blocks/SM.
// Epilogue writes tf32-PACKED output (k-perm) for the final GEMM.
// ---------------------------------------------------------------------------
#define ASTR 72
#define SMAX 20.0f

__global__ __launch_bounds__(128, 3) void attn_tc_kernel(
    const uint32_t* __restrict__ qp, const uint32_t* __restrict__ kp,
    const uint32_t* __restrict__ vt, uint32_t* __restrict__ outp)
{
    extern __shared__ uint32_t sm[];
    uint32_t* Qs = sm;                  // [128][ASTR]
    uint32_t* Ks = sm + 128 * ASTR;     // [64][ASTR]
    uint32_t* Vs = sm + 192 * ASTR;     // [64][ASTR]

    const int tid  = threadIdx.x;
    const int warp = tid >> 5;
    const int lane = tid & 31;
    const int gr   = lane >> 2;
    const int tg   = lane & 3;
    const int h    = blockIdx.y;
    const int b    = blockIdx.z;

    const int qrow0 = blockIdx.x * 128;
    const size_t bh = (size_t)b * NHEAD + h;
    const uint32_t* qbase = qp + (bh * SEQ + qrow0) * 64;

    const uint32_t qs_a = (uint32_t)__cvta_generic_to_shared(Qs);
    const uint32_t ks_a = (uint32_t)__cvta_generic_to_shared(Ks);
    const uint32_t vs_a = (uint32_t)__cvta_generic_to_shared(Vs);

    // hoisted loader addresses
    const int rr = tid >> 4;              // 0..7
    const int cc = (tid & 15) * 4;        // 0..60
    const uint32_t ksd = ks_a + (rr * ASTR + cc) * 4;
    const uint32_t vsd = vs_a + (rr * ASTR + cc) * 4;
    const uint32_t* kg = kp + bh * SEQ * 64 + rr * 64 + cc;
    const uint32_t* vg = vt + bh * 64 * SEQ + (size_t)rr * SEQ + cc;

    // Q tile: 128 rows (joins first K commit group)
#pragma unroll
    for (int n = 0; n < 16; n++)
        cp_async16(qs_a + ((rr + 8 * n) * ASTR + cc) * 4,
                   qbase + (rr + 8 * n) * 64 + cc);

    // warp's two m-tiles: rows warp*32 + {0,16} (+gr, +8)
    const int qr0 = warp * 32 + gr;       // m-tile 0
    const int qr1 = qr0 + 16;             // m-tile 1

    float of[2][8][4];
#pragma unroll
    for (int m = 0; m < 2; m++)
#pragma unroll
        for (int nt = 0; nt < 8; nt++)
#pragma unroll
            for (int c = 0; c < 4; c++) of[m][nt][c] = 0.f;

    float l00 = 0.f, l01 = 0.f, l10 = 0.f, l11 = 0.f;

    for (int k0 = 0; k0 < SEQ; k0 += 64) {
        __syncthreads();   // previous-tile reads done (covers Qs on iter 0)

#pragma unroll
        for (int n = 0; n < 8; n++)
            cp_async16(ksd + n * (8 * ASTR * 4), kg + n * (8 * 64));
        cp_commit();
#pragma unroll
        for (int n = 0; n < 8; n++)
            cp_async16(vsd + n * (8 * ASTR * 4), vg + n * (8 * SEQ));
        cp_commit();
        kg += 64 * 64;
        vg += 64;

        asm volatile("cp.async.wait_group 1;\n" ::: "memory");
        __syncthreads();

        // S = Q @ K^T for both m-tiles; each kb feeds 2 MMAs
        float sacc[2][8][4];
#pragma unroll
        for (int m = 0; m < 2; m++)
#pragma unroll
            for (int nt = 0; nt < 8; nt++)
#pragma unroll
                for (int c = 0; c < 4; c++) sacc[m][nt][c] = 0.f;

#pragma unroll
        for (int j = 0; j < 8; j++) {
            const uint2 qa0 = *(const uint2*)&Qs[qr0 * ASTR + 8 * j + 2 * tg];
            const uint2 qa1 = *(const uint2*)&Qs[(qr0 + 8) * ASTR + 8 * j + 2 * tg];
            const uint2 qb0 = *(const uint2*)&Qs[qr1 * ASTR + 8 * j + 2 * tg];
            const uint2 qb1 = *(const uint2*)&Qs[(qr1 + 8) * ASTR + 8 * j + 2 * tg];
            uint32_t a0[4] = {qa0.x, qa1.x, qa0.y, qa1.y};
            uint32_t a1[4] = {qb0.x, qb1.x, qb0.y, qb1.y};
#pragma unroll
            for (int nt = 0; nt < 8; nt++) {
                const uint2 kb = *(const uint2*)&Ks[(8 * nt + gr) * ASTR + 8 * j + 2 * tg];
                mma_tf32(sacc[0][nt], a0, (const uint32_t*)&kb, sacc[0][nt]);
                mma_tf32(sacc[1][nt], a1, (const uint32_t*)&kb, sacc[1][nt]);
            }
        }

        asm volatile("cp.async.wait_group 0;\n" ::: "memory");
        __syncthreads();

        // P = exp2(S - SMAX); O += P @ V ; each vb feeds 2 MMAs
#pragma unroll
        for (int j = 0; j < 8; j++) {
            uint32_t a0[4], a1[4];
            a0[0] = f2tf32(ex2(sacc[0][j][0] - SMAX));
            a0[1] = f2tf32(ex2(sacc[0][j][2] - SMAX));
            a0[2] = f2tf32(ex2(sacc[0][j][1] - SMAX));
            a0[3] = f2tf32(ex2(sacc[0][j][3] - SMAX));
            a1[0] = f2tf32(ex2(sacc[1][j][0] - SMAX));
            a1[1] = f2tf32(ex2(sacc[1][j][2] - SMAX));
            a1[2] = f2tf32(ex2(sacc[1][j][1] - SMAX));
            a1[3] = f2tf32(ex2(sacc[1][j][3] - SMAX));
            l00 += __uint_as_float(a0[0]) + __uint_as_float(a0[2]);
            l01 += __uint_as_float(a0[1]) + __uint_as_float(a0[3]);
            l10 += __uint_as_float(a1[0]) + __uint_as_float(a1[2]);
            l11 += __uint_as_float(a1[1]) + __uint_as_float(a1[3]);
#pragma unroll
            for (int nt = 0; nt < 8; nt++) {
                const uint2 vb = *(const uint2*)&Vs[(8 * nt + gr) * ASTR + 8 * j + 2 * tg];
                mma_tf32(of[0][nt], a0, (const uint32_t*)&vb, of[0][nt]);
                mma_tf32(of[1][nt], a1, (const uint32_t*)&vb, of[1][nt]);
            }
        }
    }

    l00 += __shfl_xor_sync(0xFFFFFFFFu, l00, 1);
    l00 += __shfl_xor_sync(0xFFFFFFFFu, l00, 2);
    l01 += __shfl_xor_sync(0xFFFFFFFFu, l01, 1);
    l01 += __shfl_xor_sync(0xFFFFFFFFu, l01, 2);
    l10 += __shfl_xor_sync(0xFFFFFFFFu, l10, 1);
    l10 += __shfl_xor_sync(0xFFFFFFFFu, l10, 2);
    l11 += __shfl_xor_sync(0xFFFFFFFFu, l11, 1);
    l11 += __shfl_xor_sync(0xFFFFFFFFu, l11, 2);
    const float inv[2][2] = {{1.f / l00, 1.f / l01}, {1.f / l10, 1.f / l11}};

    const int pe = perm8(2 * tg);
    const int po = perm8(2 * tg + 1);
#pragma unroll
    for (int m = 0; m < 2; m++) {
        const int row = qrow0 + warp * 32 + m * 16 + gr;
        uint32_t* o0 = outp + ((size_t)b * SEQ + row) * DIM + h * HDIM;
        uint32_t* o1 = o0 + 8 * DIM;
#pragma unroll
        for (int nt = 0; nt < 8; nt++) {
            o0[8 * nt + pe] = f2tf32(of[m][nt][0] * inv[m][0]);
            o0[8 * nt + po] = f2tf32(of[m][nt][1] * inv[m][0]);
            o1[8 * nt + pe] = f2tf32(of[m][nt][2] * inv[m][1]);
            o1[8 * nt + po] = f2tf32(of[m][nt][3] * inv[m][1]);
        }
    }
}

// ---------------------------------------------------------------------------
// Launch
// ---------------------------------------------------------------------------
extern "C" void kernel_launch(void* const* d_in, const int* in_sizes, int n_in,
                              void* d_out, int out_size)
{
    const float* x   = (const float*)d_in[0];
    const float* Wq  = (const float*)d_in[1];
    const float* bq  = (const float*)d_in[2];
    const float* Wk  = (const float*)d_in[3];
    const float* bk  = (const float*)d_in[4];
    const float* Wv  = (const float*)d_in[5];
    const float* bv  = (const float*)d_in[6];
    const float* Wo  = (const float*)d_in[7];
    const float* bo  = (const float*)d_in[8];
    const float* nqw = (const float*)d_in[9];
    const float* nkw = (const float*)d_in[10];
    float* out = (float*)d_out;

    float *dq, *dk, *dv;
    uint32_t *dqp, *dkp, *dvt, *dxp, *dwp, *dap;
    cudaGetSymbolAddress((void**)&dq,  g_q);
    cudaGetSymbolAddress((void**)&dk,  g_k);
    cudaGetSymbolAddress((void**)&dv,  g_v);
    cudaGetSymbolAddress((void**)&dqp, g_qp);
    cudaGetSymbolAddress((void**)&dkp, g_kp);
    cudaGetSymbolAddress((void**)&dvt, g_vt);
    cudaGetSymbolAddress((void**)&dxp, g_xp);
    cudaGetSymbolAddress((void**)&dwp, g_wp);
    cudaGetSymbolAddress((void**)&dap, g_ap);

    const int gemm_smem = 2 * 256 * GSTR * 4;       // 81920 bytes
    cudaFuncSetAttribute(gemm_pk_kernel,
                         cudaFuncAttributeMaxDynamicSharedMemorySize, gemm_smem);
    cudaFuncSetAttribute(gemm_pk_qkv_kernel,
                         cudaFuncAttributeMaxDynamicSharedMemorySize, gemm_smem);
    const int attn_smem = 4 * 64 * ASTR * 4;        // 73728 bytes
    cudaFuncSetAttribute(attn_tc_kernel,
                         cudaFuncAttributeMaxDynamicSharedMemorySize, attn_smem);

    pack_tf32_kernel<<<MROWS / 2, 256>>>(x, dxp);
    dim3 wgrid(DIM / 2, 4);
    pack_w4_kernel<<<wgrid, 256>>>(Wq, Wk, Wv, Wo, dwp);

    dim3 qkvgrid(8, 32, 3);
    gemm_pk_qkv_kernel<<<qkvgrid, 256, gemm_smem>>>(
        dxp, dwp, bq, bk, bv, dq, dk, dv);

    dim3 pgrid(MROWS, 2);
    prepack_qk_kernel<<<pgrid, 128>>>(dq, dk, nqw, nkw, dqp, dkp);
    dim3 vgrid(SEQ / 64, NHEAD, BATCH);
    prepack_v_kernel<<<vgrid, 256>>>(dv, dvt);

    dim3 agrid(SEQ / 128, NHEAD, BATCH);   // 512 blocks
    attn_tc_kernel<<<agrid, 128, attn_smem>>>(dqp, dkp, dvt, dap);

    dim3 ggrid(8, 32);
    gemm_pk_kernel<<<ggrid, 256, gemm_smem>>>(
        dap, dwp + 3 * (size_t)DIM * DIM, bo, out);
}

// round 13
// speedup vs baseline: 1.3534x; 1.3534x over previous
#include <cuda_runtime.h>
#include <cuda_bf16.h>
#include <math.h>
#include <stdint.h>

// Problem constants
#define BATCH 2
#define SEQ   2048
#define DIM   1024
#define NHEAD 16
#define HDIM  64
#define MROWS (BATCH*SEQ)   // 4096

// Scratch buffers (allocation-free rule: static device globals)
__device__ float    g_q[MROWS * DIM];
__device__ float    g_k[MROWS * DIM];
__device__ float    g_v[MROWS * DIM];
__device__ uint32_t g_qp[MROWS * DIM];      // tf32 packed Q [b][h][s][hdperm]
__device__ uint32_t g_kp[MROWS * DIM];      // tf32 packed K [b][h][sperm][hdperm]
__device__ uint32_t g_vt[MROWS * DIM];      // tf32 packed V [b][h][hd][keyperm]
__device__ uint32_t g_xp[MROWS * DIM];      // tf32 packed X (k-perm)
__device__ uint32_t g_wp[4 * DIM * DIM];    // tf32 packed Wq,Wk,Wv,Wo (k-perm)
__device__ uint32_t g_ap[MROWS * DIM];      // tf32 packed attn-out (k-perm)

__device__ __forceinline__ uint32_t f2tf32(float f) {
    uint32_t u;
    asm("cvt.rna.tf32.f32 %0, %1;" : "=r"(u) : "f"(f));
    return u;
}

__device__ __forceinline__ float ex2(float x) {
    float y;
    asm("ex2.approx.f32 %0, %1;" : "=f"(y) : "f"(x));
    return y;
}

__device__ __forceinline__ void mma_tf32(float* d, const uint32_t* a,
                                         const uint32_t* b, const float* c) {
    asm volatile(
        "mma.sync.aligned.m16n8k8.row.col.f32.tf32.tf32.f32 "
        "{%0,%1,%2,%3}, {%4,%5,%6,%7}, {%8,%9}, {%10,%11,%12,%13};\n"
        : "=f"(d[0]), "=f"(d[1]), "=f"(d[2]), "=f"(d[3])
        : "r"(a[0]), "r"(a[1]), "r"(a[2]), "r"(a[3]),
          "r"(b[0]), "r"(b[1]),
          "f"(c[0]), "f"(c[1]), "f"(c[2]), "f"(c[3]));
}

__device__ __forceinline__ void cp_async16(uint32_t sm_addr, const void* gptr) {
    asm volatile("cp.async.cg.shared.global [%0], [%1], 16;\n"
                 :: "r"(sm_addr), "l"(gptr));
}
__device__ __forceinline__ void cp_commit() {
    asm volatile("cp.async.commit_group;\n" ::: "memory");
}

// perm within groups of 8: logical l -> 2*(l%4) + (l/4)
__device__ __forceinline__ int perm8(int l) {
    return (l & ~7) | (2 * (l & 3)) | ((l >> 2) & 1);
}

// ---------------------------------------------------------------------------
// Pack fp32 [rows][1024] -> tf32 with perm8 on the k axis. 256 thr, 2 rows/blk.
// ---------------------------------------------------------------------------
__global__ __launch_bounds__(256) void pack_tf32_kernel(
    const float* __restrict__ in, uint32_t* __restrict__ out)
{
    const int t = threadIdx.x;
    const size_t base = ((size_t)blockIdx.x * 2 + (t >> 7)) * DIM + (t & 127) * 8;
    const float4 v0 = *(const float4*)(in + base);
    const float4 v1 = *(const float4*)(in + base + 4);
    uint4 o0, o1;
    o0.x = f2tf32(v0.x); o0.y = f2tf32(v1.x);
    o0.z = f2tf32(v0.y); o0.w = f2tf32(v1.y);
    o1.x = f2tf32(v0.z); o1.y = f2tf32(v1.z);
    o1.z = f2tf32(v0.w); o1.w = f2tf32(v1.w);
    *(uint4*)(out + base)     = o0;
    *(uint4*)(out + base + 4) = o1;
}

// Fused pack of the 4 weight matrices: grid (DIM/2, 4)
__global__ __launch_bounds__(256) void pack_w4_kernel(
    const float* __restrict__ Wq, const float* __restrict__ Wk,
    const float* __restrict__ Wv, const float* __restrict__ Wo,
    uint32_t* __restrict__ out)
{
    const float* W;
    switch (blockIdx.y) {
        case 0: W = Wq; break;
        case 1: W = Wk; break;
        case 2: W = Wv; break;
        default: W = Wo; break;
    }
    uint32_t* o = out + (size_t)blockIdx.y * DIM * DIM;
    const int t = threadIdx.x;
    const size_t base = ((size_t)blockIdx.x * 2 + (t >> 7)) * DIM + (t & 127) * 8;
    const float4 v0 = *(const float4*)(W + base);
    const float4 v1 = *(const float4*)(W + base + 4);
    uint4 o0, o1;
    o0.x = f2tf32(v0.x); o0.y = f2tf32(v1.x);
    o0.z = f2tf32(v0.y); o0.w = f2tf32(v1.y);
    o1.x = f2tf32(v0.z); o1.y = f2tf32(v1.z);
    o1.z = f2tf32(v0.w); o1.w = f2tf32(v1.w);
    *(uint4*)(o + base)     = o0;
    *(uint4*)(o + base + 4) = o1;
}

// ---------------------------------------------------------------------------
// Packed tf32 GEMM v2: 128-thread blocks, 4 blocks/SM (attention-proven
// concurrency), tile 128x64, k-tile 16, warp-tile 64x32 (2m x 2n warps).
// 2-stage cp.async, ONE barrier per k-tile. Stride 24 (==8 mod 32):
// fragment LDS.64 conflict-free per 16-lane phase. smem 36.9KB/block.
// ---------------------------------------------------------------------------
#define G2STR 24
#define G2NKT (DIM / 16)   // 64 k-tiles

__device__ __forceinline__ void gemm_s4_body(
    const uint32_t* __restrict__ A, const uint32_t* __restrict__ W,
    const float* __restrict__ bias, float* __restrict__ C,
    int bx, int by, uint32_t* gsm)
{
    const int tid  = threadIdx.x;
    const int bm   = by * 128;
    const int bn   = bx * 64;
    const int warp = tid >> 5;
    const int lane = tid & 31;
    const int wm   = (warp >> 1) * 64;    // 0 or 64
    const int wn   = (warp & 1) * 32;     // 0 or 32
    const int gr   = lane >> 2;
    const int tg   = lane & 3;

    const uint32_t sm_a = (uint32_t)__cvta_generic_to_shared(gsm);

    // loader: r0 = row slot (0..31), cw = word offset (0,4,8,12)
    const int r0 = tid >> 2;
    const int cw = (tid & 3) * 4;
    const uint32_t* arow = A + (size_t)(bm + r0) * DIM + cw;
    const uint32_t* wrow = W + (size_t)(bn + r0) * DIM + cw;

    float acc[4][4][4];
#pragma unroll
    for (int i = 0; i < 4; i++)
#pragma unroll
        for (int j = 0; j < 4; j++)
#pragma unroll
            for (int c = 0; c < 4; c++) acc[i][j][c] = 0.f;

    auto issue = [&](int t) {
        const int st = t & 1;
        const uint32_t base = sm_a + st * (192 * G2STR * 4);
        const uint32_t* ag = arow + t * 16;
        const uint32_t* wg = wrow + t * 16;
#pragma unroll
        for (int n = 0; n < 4; n++)
            cp_async16(base + ((r0 + 32 * n) * G2STR + cw) * 4,
                       ag + (size_t)(32 * n) * DIM);
#pragma unroll
        for (int n = 0; n < 2; n++)
            cp_async16(base + ((128 + r0 + 32 * n) * G2STR + cw) * 4,
                       wg + (size_t)(32 * n) * DIM);
        cp_commit();
    };

    issue(0);

    for (int t = 0; t < G2NKT; t++) {
        asm volatile("cp.async.wait_group 0;\n" ::: "memory");
        __syncthreads();
        if (t + 1 < G2NKT) issue(t + 1);

        const uint32_t* Ab = gsm + (t & 1) * 192 * G2STR;
        const uint32_t* Bb = Ab + 128 * G2STR;

#pragma unroll
        for (int ks = 0; ks < 2; ks++) {
            const int kk = ks * 8;
            uint32_t af[4][4], bf[4][2];
#pragma unroll
            for (int i = 0; i < 4; i++) {
                const int r = wm + i * 16 + gr;
                const uint2 a02 = *(const uint2*)&Ab[r * G2STR + kk + 2 * tg];
                const uint2 a13 = *(const uint2*)&Ab[(r + 8) * G2STR + kk + 2 * tg];
                af[i][0] = a02.x; af[i][1] = a13.x;
                af[i][2] = a02.y; af[i][3] = a13.y;
            }
#pragma unroll
            for (int j = 0; j < 4; j++) {
                const int n = wn + j * 8 + gr;
                const uint2 bb = *(const uint2*)&Bb[n * G2STR + kk + 2 * tg];
                bf[j][0] = bb.x; bf[j][1] = bb.y;
            }
#pragma unroll
            for (int i = 0; i < 4; i++)
#pragma unroll
                for (int j = 0; j < 4; j++)
                    mma_tf32(acc[i][j], af[i], bf[j], acc[i][j]);
        }
    }

#pragma unroll
    for (int i = 0; i < 4; i++) {
#pragma unroll
        for (int j = 0; j < 4; j++) {
            const int row = bm + wm + i * 16 + gr;
            const int col = bn + wn + j * 8 + 2 * tg;
            const float2 b01 = *(const float2*)(bias + col);
            float2 o0, o1;
            o0.x = acc[i][j][0] + b01.x;
            o0.y = acc[i][j][1] + b01.y;
            o1.x = acc[i][j][2] + b01.x;
            o1.y = acc[i][j][3] + b01.y;
            *(float2*)(C + (size_t)row * DIM + col)       = o0;
            *(float2*)(C + (size_t)(row + 8) * DIM + col) = o1;
        }
    }
}

__global__ __launch_bounds__(128, 4) void gemm_s4_kernel(
    const uint32_t* __restrict__ A, const uint32_t* __restrict__ W,
    const float* __restrict__ bias, float* __restrict__ C)
{
    extern __shared__ uint32_t gsm[];
    gemm_s4_body(A, W, bias, C, blockIdx.x, blockIdx.y, gsm);
}

__global__ __launch_bounds__(128, 4) void gemm_s4_qkv_kernel(
    const uint32_t* __restrict__ A, const uint32_t* __restrict__ Wp,
    const float* __restrict__ bq, const float* __restrict__ bk,
    const float* __restrict__ bv,
    float* __restrict__ Cq, float* __restrict__ Ck, float* __restrict__ Cv)
{
    extern __shared__ uint32_t gsm[];
    const float* b; float* C;
    if (blockIdx.z == 0)      { b = bq; C = Cq; }
    else if (blockIdx.z == 1) { b = bk; C = Ck; }
    else                      { b = bv; C = Cv; }
    gemm_s4_body(A, Wp + (size_t)blockIdx.z * DIM * DIM, b, C,
                 blockIdx.x, blockIdx.y, gsm);
}

// ---------------------------------------------------------------------------
// Prepack Q/K v2: fused RMSNorm + tf32 + head split + perm, vectorized stores.
// ---------------------------------------------------------------------------
__global__ __launch_bounds__(128) void prepack_qk_kernel(
    const float* __restrict__ qin, const float* __restrict__ kin,
    const float* __restrict__ nqw, const float* __restrict__ nkw,
    uint32_t* __restrict__ qp, uint32_t* __restrict__ kp)
{
    const int row = blockIdx.x;
    const int isk = blockIdx.y;
    const float* src = (isk ? kin : qin) + (size_t)row * DIM;
    const float* w   = isk ? nkw : nqw;
    uint32_t* dstbuf = isk ? kp : qp;
    const int t = threadIdx.x;

    const float4 v0 = *(const float4*)(src + t * 8);
    const float4 v1 = *(const float4*)(src + t * 8 + 4);
    float ss = v0.x * v0.x + v0.y * v0.y + v0.z * v0.z + v0.w * v0.w
             + v1.x * v1.x + v1.y * v1.y + v1.z * v1.z + v1.w * v1.w;
#pragma unroll
    for (int off = 16; off > 0; off >>= 1)
        ss += __shfl_xor_sync(0xFFFFFFFFu, ss, off);
    __shared__ float red[4];
    if ((t & 31) == 0) red[t >> 5] = ss;
    __syncthreads();
    const float total = red[0] + red[1] + red[2] + red[3];

    const float SCALE = 0.125f * 1.4426950408889634f;
    float norm = rsqrtf(total * (1.0f / DIM) + 1e-6f);
    if (!isk) norm *= SCALE;

    const int b = row >> 11;
    const int s = row & 2047;
    const int srow = isk ? perm8(s) : s;
    const int h = t >> 3;
    const float4 w0 = *(const float4*)(w + t * 8);
    const float4 w1 = *(const float4*)(w + t * 8 + 4);

    const float y0 = v0.x * norm * w0.x, y1 = v0.y * norm * w0.y;
    const float y2 = v0.z * norm * w0.z, y3 = v0.w * norm * w0.w;
    const float y4 = v1.x * norm * w1.x, y5 = v1.y * norm * w1.y;
    const float y6 = v1.z * norm * w1.z, y7 = v1.w * norm * w1.w;

    uint32_t* dst = dstbuf + (((size_t)b * NHEAD + h) * SEQ + srow) * 64
                  + (t & 7) * 8;
    uint4 o0, o1;
    o0.x = f2tf32(y0); o0.y = f2tf32(y4);
    o0.z = f2tf32(y1); o0.w = f2tf32(y5);
    o1.x = f2tf32(y2); o1.y = f2tf32(y6);
    o1.z = f2tf32(y3); o1.w = f2tf32(y7);
    *(uint4*)(dst)     = o0;
    *(uint4*)(dst + 4) = o1;
}

// ---------------------------------------------------------------------------
// Prepack V: transpose to [b][h][hd][key-perm], tf32.
// ---------------------------------------------------------------------------
__global__ __launch_bounds__(256) void prepack_v_kernel(
    const float* __restrict__ vin, uint32_t* __restrict__ vt)
{
    __shared__ float ts[64][65];
    const int t  = threadIdx.x;
    const int k0 = blockIdx.x * 64;
    const int h  = blockIdx.y;
    const int b  = blockIdx.z;

    for (int i = t; i < 64 * 16; i += 256) {
        const int r  = i >> 4;
        const int c4 = i & 15;
        const float4 vv = *(const float4*)(
            vin + ((size_t)b * SEQ + k0 + r) * DIM + h * HDIM + c4 * 4);
        ts[r][c4 * 4 + 0] = vv.x;
        ts[r][c4 * 4 + 1] = vv.y;
        ts[r][c4 * 4 + 2] = vv.z;
        ts[r][c4 * 4 + 3] = vv.w;
    }
    __syncthreads();

    const int hd = t >> 2;
    uint32_t* dst = vt + (((size_t)b * NHEAD + h) * 64 + hd) * SEQ + k0;
#pragma unroll
    for (int g2 = 0; g2 < 2; g2++) {
        const int g = (t & 3) * 2 + g2;
        uint4 w0, w1;
        w0.x = f2tf32(ts[g * 8 + 0][hd]); w0.y = f2tf32(ts[g * 8 + 4][hd]);
        w0.z = f2tf32(ts[g * 8 + 1][hd]); w0.w = f2tf32(ts[g * 8 + 5][hd]);
        w1.x = f2tf32(ts[g * 8 + 2][hd]); w1.y = f2tf32(ts[g * 8 + 6][hd]);
        w1.z = f2tf32(ts[g * 8 + 3][hd]); w1.w = f2tf32(ts[g * 8 + 7][hd]);
        *(uint4*)(dst + g * 8)     = w0;
        *(uint4*)(dst + g * 8 + 4) = w1;
    }
}

// ---------------------------------------------------------------------------
// Tensor-core flash attention v5 (R11 EXACT, measured best): static-max
// softmax, hoisted cp.async addressing, split-commit K/V, packed epilogue.
// ---------------------------------------------------------------------------
#define ASTR 72
#define SMAX 20.0f

__global__ __launch_bounds__(128, 4) void attn_tc_kernel(
    const uint32_t* __restrict__ qp, const uint32_t* __restrict__ kp,
    const uint32_t* __restrict__ vt, uint32_t* __restrict__ outp)
{
    extern __shared__ uint32_t sm[];
    uint32_t* Qs = sm;
    uint32_t* Ks = sm + 64 * ASTR;
    uint32_t* Vs = sm + 128 * ASTR;

    const int tid  = threadIdx.x;
    const int warp = tid >> 5;
    const int lane = tid & 31;
    const int gr   = lane >> 2;
    const int tg   = lane & 3;
    const int h    = blockIdx.y;
    const int b    = blockIdx.z;

    const int qrow0 = blockIdx.x * 64;
    const size_t bh = (size_t)b * NHEAD + h;
    const uint32_t* qbase = qp + (bh * SEQ + qrow0) * 64;

    const uint32_t qs_a = (uint32_t)__cvta_generic_to_shared(Qs);
    const uint32_t ks_a = (uint32_t)__cvta_generic_to_shared(Ks);
    const uint32_t vs_a = (uint32_t)__cvta_generic_to_shared(Vs);

    const int rr = tid >> 4;
    const int cc = (tid & 15) * 4;
    const uint32_t ksd = ks_a + (rr * ASTR + cc) * 4;
    const uint32_t vsd = vs_a + (rr * ASTR + cc) * 4;
    const uint32_t* kg = kp + bh * SEQ * 64 + rr * 64 + cc;
    const uint32_t* vg = vt + bh * 64 * SEQ + (size_t)rr * SEQ + cc;

#pragma unroll
    for (int n = 0; n < 8; n++)
        cp_async16(qs_a + ((rr + 8 * n) * ASTR + cc) * 4,
                   qbase + (rr + 8 * n) * 64 + cc);

    const int qr = warp * 16 + gr;

    float of[8][4];
#pragma unroll
    for (int nt = 0; nt < 8; nt++)
#pragma unroll
        for (int c = 0; c < 4; c++) of[nt][c] = 0.f;

    float l0 = 0.f, l1 = 0.f;

    for (int k0 = 0; k0 < SEQ; k0 += 64) {
        __syncthreads();

#pragma unroll
        for (int n = 0; n < 8; n++)
            cp_async16(ksd + n * (8 * ASTR * 4), kg + n * (8 * 64));
        cp_commit();
#pragma unroll
        for (int n = 0; n < 8; n++)
            cp_async16(vsd + n * (8 * ASTR * 4), vg + n * (8 * SEQ));
        cp_commit();
        kg += 64 * 64;
        vg += 64;

        asm volatile("cp.async.wait_group 1;\n" ::: "memory");
        __syncthreads();

        float sacc[8][4];
#pragma unroll
        for (int nt = 0; nt < 8; nt++)
#pragma unroll
            for (int c = 0; c < 4; c++) sacc[nt][c] = 0.f;

#pragma unroll
        for (int j = 0; j < 8; j++) {
            const uint2 q0 = *(const uint2*)&Qs[qr * ASTR + 8 * j + 2 * tg];
            const uint2 q1 = *(const uint2*)&Qs[(qr + 8) * ASTR + 8 * j + 2 * tg];
            uint32_t a[4] = {q0.x, q1.x, q0.y, q1.y};
#pragma unroll
            for (int nt = 0; nt < 8; nt++) {
                const uint2 kb = *(const uint2*)&Ks[(8 * nt + gr) * ASTR + 8 * j + 2 * tg];
                mma_tf32(sacc[nt], a, (const uint32_t*)&kb, sacc[nt]);
            }
        }

        asm volatile("cp.async.wait_group 0;\n" ::: "memory");
        __syncthreads();

#pragma unroll
        for (int j = 0; j < 8; j++) {
            uint32_t a[4];
            a[0] = f2tf32(ex2(sacc[j][0] - SMAX));
            a[1] = f2tf32(ex2(sacc[j][2] - SMAX));
            a[2] = f2tf32(ex2(sacc[j][1] - SMAX));
            a[3] = f2tf32(ex2(sacc[j][3] - SMAX));
            l0 += __uint_as_float(a[0]) + __uint_as_float(a[2]);
            l1 += __uint_as_float(a[1]) + __uint_as_float(a[3]);
#pragma unroll
            for (int nt = 0; nt < 8; nt++) {
                const uint2 vb = *(const uint2*)&Vs[(8 * nt + gr) * ASTR + 8 * j + 2 * tg];
                mma_tf32(of[nt], a, (const uint32_t*)&vb, of[nt]);
            }
        }
    }

    l0 += __shfl_xor_sync(0xFFFFFFFFu, l0, 1);
    l0 += __shfl_xor_sync(0xFFFFFFFFu, l0, 2);
    l1 += __shfl_xor_sync(0xFFFFFFFFu, l1, 1);
    l1 += __shfl_xor_sync(0xFFFFFFFFu, l1, 2);
    const float inv0 = 1.f / l0;
    const float inv1 = 1.f / l1;

    const int pe = perm8(2 * tg);
    const int po = perm8(2 * tg + 1);
    uint32_t* o0 = outp + ((size_t)b * SEQ + qrow0 + qr) * DIM + h * HDIM;
    uint32_t* o1 = o0 + 8 * DIM;
#pragma unroll
    for (int nt = 0; nt < 8; nt++) {
        o0[8 * nt + pe] = f2tf32(of[nt][0] * inv0);
        o0[8 * nt + po] = f2tf32(of[nt][1] * inv0);
        o1[8 * nt + pe] = f2tf32(of[nt][2] * inv1);
        o1[8 * nt + po] = f2tf32(of[nt][3] * inv1);
    }
}

// ---------------------------------------------------------------------------
// Launch
// ---------------------------------------------------------------------------
extern "C" void kernel_launch(void* const* d_in, const int* in_sizes, int n_in,
                              void* d_out, int out_size)
{
    const float* x   = (const float*)d_in[0];
    const float* Wq  = (const float*)d_in[1];
    const float* bq  = (const float*)d_in[2];
    const float* Wk  = (const float*)d_in[3];
    const float* bk  = (const float*)d_in[4];
    const float* Wv  = (const float*)d_in[5];
    const float* bv  = (const float*)d_in[6];
    const float* Wo  = (const float*)d_in[7];
    const float* bo  = (const float*)d_in[8];
    const float* nqw = (const float*)d_in[9];
    const float* nkw = (const float*)d_in[10];
    float* out = (float*)d_out;

    float *dq, *dk, *dv;
    uint32_t *dqp, *dkp, *dvt, *dxp, *dwp, *dap;
    cudaGetSymbolAddress((void**)&dq,  g_q);
    cudaGetSymbolAddress((void**)&dk,  g_k);
    cudaGetSymbolAddress((void**)&dv,  g_v);
    cudaGetSymbolAddress((void**)&dqp, g_qp);
    cudaGetSymbolAddress((void**)&dkp, g_kp);
    cudaGetSymbolAddress((void**)&dvt, g_vt);
    cudaGetSymbolAddress((void**)&dxp, g_xp);
    cudaGetSymbolAddress((void**)&dwp, g_wp);
    cudaGetSymbolAddress((void**)&dap, g_ap);

    const int gemm_smem = 2 * 192 * G2STR * 4;      // 36864 bytes
    cudaFuncSetAttribute(gemm_s4_kernel,
                         cudaFuncAttributeMaxDynamicSharedMemorySize, gemm_smem);
    cudaFuncSetAttribute(gemm_s4_qkv_kernel,
                         cudaFuncAttributeMaxDynamicSharedMemorySize, gemm_smem);
    const int attn_smem = 3 * 64 * ASTR * 4;        // 55296 bytes
    cudaFuncSetAttribute(attn_tc_kernel,
                         cudaFuncAttributeMaxDynamicSharedMemorySize, attn_smem);

    pack_tf32_kernel<<<MROWS / 2, 256>>>(x, dxp);
    dim3 wgrid(DIM / 2, 4);
    pack_w4_kernel<<<wgrid, 256>>>(Wq, Wk, Wv, Wo, dwp);

    dim3 qkvgrid(DIM / 64, MROWS / 128, 3);   // (16, 32, 3)
    gemm_s4_qkv_kernel<<<qkvgrid, 128, gemm_smem>>>(
        dxp, dwp, bq, bk, bv, dq, dk, dv);

    dim3 pgrid(MROWS, 2);
    prepack_qk_kernel<<<pgrid, 128>>>(dq, dk, nqw, nkw, dqp, dkp);
    dim3 vgrid(SEQ / 64, NHEAD, BATCH);
    prepack_v_kernel<<<vgrid, 256>>>(dv, dvt);

    dim3 agrid(SEQ / 64, NHEAD, BATCH);
    attn_tc_kernel<<<agrid, 128, attn_smem>>>(dqp, dkp, dvt, dap);

    dim3 ggrid(DIM / 64, MROWS / 128);        // (16, 32)
    gemm_s4_kernel<<<ggrid, 128, gemm_smem>>>(
        dap, dwp + 3 * (size_t)DIM * DIM, bo, out);
}

// round 14
// speedup vs baseline: 1.3577x; 1.0031x over previous
#include <cuda_runtime.h>
#include <cuda_bf16.h>
#include <math.h>
#include <stdint.h>

// Problem constants
#define BATCH 2
#define SEQ   2048
#define DIM   1024
#define NHEAD 16
#define HDIM  64
#define MROWS (BATCH*SEQ)   // 4096

// Scratch buffers (allocation-free rule: static device globals)
__device__ float    g_q[MROWS * DIM];
__device__ float    g_k[MROWS * DIM];
__device__ float    g_v[MROWS * DIM];
__device__ uint32_t g_qp[MROWS * DIM];      // tf32 packed Q [b][h][s][hdperm]
__device__ uint32_t g_kp[MROWS * DIM];      // tf32 packed K [b][h][sperm][hdperm]
__device__ uint32_t g_vt[MROWS * DIM];      // tf32 packed V [b][h][hd][keyperm]
__device__ uint32_t g_xp[MROWS * DIM];      // tf32 packed X (k-perm)
__device__ uint32_t g_wp[4 * DIM * DIM];    // tf32 packed Wq,Wk,Wv,Wo (k-perm)
__device__ uint32_t g_ap[MROWS * DIM];      // tf32 packed attn-out (k-perm)

__device__ __forceinline__ uint32_t f2tf32(float f) {
    uint32_t u;
    asm("cvt.rna.tf32.f32 %0, %1;" : "=r"(u) : "f"(f));
    return u;
}

__device__ __forceinline__ float ex2(float x) {
    float y;
    asm("ex2.approx.f32 %0, %1;" : "=f"(y) : "f"(x));
    return y;
}

__device__ __forceinline__ void mma_tf32(float* d, const uint32_t* a,
                                         const uint32_t* b, const float* c) {
    asm volatile(
        "mma.sync.aligned.m16n8k8.row.col.f32.tf32.tf32.f32 "
        "{%0,%1,%2,%3}, {%4,%5,%6,%7}, {%8,%9}, {%10,%11,%12,%13};\n"
        : "=f"(d[0]), "=f"(d[1]), "=f"(d[2]), "=f"(d[3])
        : "r"(a[0]), "r"(a[1]), "r"(a[2]), "r"(a[3]),
          "r"(b[0]), "r"(b[1]),
          "f"(c[0]), "f"(c[1]), "f"(c[2]), "f"(c[3]));
}

__device__ __forceinline__ void cp_async16(uint32_t sm_addr, const void* gptr) {
    asm volatile("cp.async.cg.shared.global [%0], [%1], 16;\n"
                 :: "r"(sm_addr), "l"(gptr));
}
__device__ __forceinline__ void cp_commit() {
    asm volatile("cp.async.commit_group;\n" ::: "memory");
}

// perm within groups of 8: logical l -> 2*(l%4) + (l/4)
__device__ __forceinline__ int perm8(int l) {
    return (l & ~7) | (2 * (l & 3)) | ((l >> 2) & 1);
}

// ---------------------------------------------------------------------------
// Pack fp32 [rows][1024] -> tf32 with perm8 on the k axis. 256 thr, 2 rows/blk.
// ---------------------------------------------------------------------------
__global__ __launch_bounds__(256) void pack_tf32_kernel(
    const float* __restrict__ in, uint32_t* __restrict__ out)
{
    const int t = threadIdx.x;
    const size_t base = ((size_t)blockIdx.x * 2 + (t >> 7)) * DIM + (t & 127) * 8;
    const float4 v0 = *(const float4*)(in + base);
    const float4 v1 = *(const float4*)(in + base + 4);
    uint4 o0, o1;
    o0.x = f2tf32(v0.x); o0.y = f2tf32(v1.x);
    o0.z = f2tf32(v0.y); o0.w = f2tf32(v1.y);
    o1.x = f2tf32(v0.z); o1.y = f2tf32(v1.z);
    o1.z = f2tf32(v0.w); o1.w = f2tf32(v1.w);
    *(uint4*)(out + base)     = o0;
    *(uint4*)(out + base + 4) = o1;
}

// Fused pack of the 4 weight matrices: grid (DIM/2, 4)
__global__ __launch_bounds__(256) void pack_w4_kernel(
    const float* __restrict__ Wq, const float* __restrict__ Wk,
    const float* __restrict__ Wv, const float* __restrict__ Wo,
    uint32_t* __restrict__ out)
{
    const float* W;
    switch (blockIdx.y) {
        case 0: W = Wq; break;
        case 1: W = Wk; break;
        case 2: W = Wv; break;
        default: W = Wo; break;
    }
    uint32_t* o = out + (size_t)blockIdx.y * DIM * DIM;
    const int t = threadIdx.x;
    const size_t base = ((size_t)blockIdx.x * 2 + (t >> 7)) * DIM + (t & 127) * 8;
    const float4 v0 = *(const float4*)(W + base);
    const float4 v1 = *(const float4*)(W + base + 4);
    uint4 o0, o1;
    o0.x = f2tf32(v0.x); o0.y = f2tf32(v1.x);
    o0.z = f2tf32(v0.y); o0.w = f2tf32(v1.y);
    o1.x = f2tf32(v0.z); o1.y = f2tf32(v1.z);
    o1.z = f2tf32(v0.w); o1.w = f2tf32(v1.w);
    *(uint4*)(o + base)     = o0;
    *(uint4*)(o + base + 4) = o1;
}

// ---------------------------------------------------------------------------
// Packed tf32 GEMM v3: 128-thread blocks, 4 blocks/SM (R13-proven), tile
// 128x64, k-tile 16, warp-tile 64x32, THREE-stage cp.async pipeline with
// wait_group 1 (each load gets ~2 compute phases of slack). ONE barrier per
// k-tile: issue(t+2) targets the buffer consumed in compute(t-1), which this
// iteration's barrier already protects. Stride 24 (==8 mod 32): conflict-free.
// smem 55.3KB/block -> 4 blocks = 221KB.
// ---------------------------------------------------------------------------
#define G2STR 24
#define G2NKT (DIM / 16)   // 64 k-tiles

__device__ __forceinline__ void gemm_s4_body(
    const uint32_t* __restrict__ A, const uint32_t* __restrict__ W,
    const float* __restrict__ bias, float* __restrict__ C,
    int bx, int by, uint32_t* gsm)
{
    const int tid  = threadIdx.x;
    const int bm   = by * 128;
    const int bn   = bx * 64;
    const int warp = tid >> 5;
    const int lane = tid & 31;
    const int wm   = (warp >> 1) * 64;    // 0 or 64
    const int wn   = (warp & 1) * 32;     // 0 or 32
    const int gr   = lane >> 2;
    const int tg   = lane & 3;

    const uint32_t sm_a = (uint32_t)__cvta_generic_to_shared(gsm);

    // loader: r0 = row slot (0..31), cw = word offset (0,4,8,12)
    const int r0 = tid >> 2;
    const int cw = (tid & 3) * 4;
    const uint32_t* arow = A + (size_t)(bm + r0) * DIM + cw;
    const uint32_t* wrow = W + (size_t)(bn + r0) * DIM + cw;

    float acc[4][4][4];
#pragma unroll
    for (int i = 0; i < 4; i++)
#pragma unroll
        for (int j = 0; j < 4; j++)
#pragma unroll
            for (int c = 0; c < 4; c++) acc[i][j][c] = 0.f;

    auto issue = [&](int t, int st) {
        const uint32_t base = sm_a + st * (192 * G2STR * 4);
        const uint32_t* ag = arow + t * 16;
        const uint32_t* wg = wrow + t * 16;
#pragma unroll
        for (int n = 0; n < 4; n++)
            cp_async16(base + ((r0 + 32 * n) * G2STR + cw) * 4,
                       ag + (size_t)(32 * n) * DIM);
#pragma unroll
        for (int n = 0; n < 2; n++)
            cp_async16(base + ((128 + r0 + 32 * n) * G2STR + cw) * 4,
                       wg + (size_t)(32 * n) * DIM);
        cp_commit();
    };

    issue(0, 0);
    issue(1, 1);

    int st_c = 0;   // compute stage
    int st_i = 2;   // issue stage
    for (int t = 0; t < G2NKT; t++) {
        asm volatile("cp.async.wait_group 1;\n" ::: "memory");
        __syncthreads();
        if (t + 2 < G2NKT) issue(t + 2, st_i);

        const uint32_t* Ab = gsm + st_c * 192 * G2STR;
        const uint32_t* Bb = Ab + 128 * G2STR;

#pragma unroll
        for (int ks = 0; ks < 2; ks++) {
            const int kk = ks * 8;
            uint32_t af[4][4], bf[4][2];
#pragma unroll
            for (int i = 0; i < 4; i++) {
                const int r = wm + i * 16 + gr;
                const uint2 a02 = *(const uint2*)&Ab[r * G2STR + kk + 2 * tg];
                const uint2 a13 = *(const uint2*)&Ab[(r + 8) * G2STR + kk + 2 * tg];
                af[i][0] = a02.x; af[i][1] = a13.x;
                af[i][2] = a02.y; af[i][3] = a13.y;
            }
#pragma unroll
            for (int j = 0; j < 4; j++) {
                const int n = wn + j * 8 + gr;
                const uint2 bb = *(const uint2*)&Bb[n * G2STR + kk + 2 * tg];
                bf[j][0] = bb.x; bf[j][1] = bb.y;
            }
#pragma unroll
            for (int i = 0; i < 4; i++)
#pragma unroll
                for (int j = 0; j < 4; j++)
                    mma_tf32(acc[i][j], af[i], bf[j], acc[i][j]);
        }

        st_c = (st_c == 2) ? 0 : st_c + 1;
        st_i = (st_i == 2) ? 0 : st_i + 1;
    }

#pragma unroll
    for (int i = 0; i < 4; i++) {
#pragma unroll
        for (int j = 0; j < 4; j++) {
            const int row = bm + wm + i * 16 + gr;
            const int col = bn + wn + j * 8 + 2 * tg;
            const float2 b01 = *(const float2*)(bias + col);
            float2 o0, o1;
            o0.x = acc[i][j][0] + b01.x;
            o0.y = acc[i][j][1] + b01.y;
            o1.x = acc[i][j][2] + b01.x;
            o1.y = acc[i][j][3] + b01.y;
            *(float2*)(C + (size_t)row * DIM + col)       = o0;
            *(float2*)(C + (size_t)(row + 8) * DIM + col) = o1;
        }
    }
}

__global__ __launch_bounds__(128, 4) void gemm_s4_kernel(
    const uint32_t* __restrict__ A, const uint32_t* __restrict__ W,
    const float* __restrict__ bias, float* __restrict__ C)
{
    extern __shared__ uint32_t gsm[];
    gemm_s4_body(A, W, bias, C, blockIdx.x, blockIdx.y, gsm);
}

__global__ __launch_bounds__(128, 4) void gemm_s4_qkv_kernel(
    const uint32_t* __restrict__ A, const uint32_t* __restrict__ Wp,
    const float* __restrict__ bq, const float* __restrict__ bk,
    const float* __restrict__ bv,
    float* __restrict__ Cq, float* __restrict__ Ck, float* __restrict__ Cv)
{
    extern __shared__ uint32_t gsm[];
    const float* b; float* C;
    if (blockIdx.z == 0)      { b = bq; C = Cq; }
    else if (blockIdx.z == 1) { b = bk; C = Ck; }
    else                      { b = bv; C = Cv; }
    gemm_s4_body(A, Wp + (size_t)blockIdx.z * DIM * DIM, b, C,
                 blockIdx.x, blockIdx.y, gsm);
}

// ---------------------------------------------------------------------------
// Prepack Q/K v2: fused RMSNorm + tf32 + head split + perm, vectorized stores.
// ---------------------------------------------------------------------------
__global__ __launch_bounds__(128) void prepack_qk_kernel(
    const float* __restrict__ qin, const float* __restrict__ kin,
    const float* __restrict__ nqw, const float* __restrict__ nkw,
    uint32_t* __restrict__ qp, uint32_t* __restrict__ kp)
{
    const int row = blockIdx.x;
    const int isk = blockIdx.y;
    const float* src = (isk ? kin : qin) + (size_t)row * DIM;
    const float* w   = isk ? nkw : nqw;
    uint32_t* dstbuf = isk ? kp : qp;
    const int t = threadIdx.x;

    const float4 v0 = *(const float4*)(src + t * 8);
    const float4 v1 = *(const float4*)(src + t * 8 + 4);
    float ss = v0.x * v0.x + v0.y * v0.y + v0.z * v0.z + v0.w * v0.w
             + v1.x * v1.x + v1.y * v1.y + v1.z * v1.z + v1.w * v1.w;
#pragma unroll
    for (int off = 16; off > 0; off >>= 1)
        ss += __shfl_xor_sync(0xFFFFFFFFu, ss, off);
    __shared__ float red[4];
    if ((t & 31) == 0) red[t >> 5] = ss;
    __syncthreads();
    const float total = red[0] + red[1] + red[2] + red[3];

    const float SCALE = 0.125f * 1.4426950408889634f;
    float norm = rsqrtf(total * (1.0f / DIM) + 1e-6f);
    if (!isk) norm *= SCALE;

    const int b = row >> 11;
    const int s = row & 2047;
    const int srow = isk ? perm8(s) : s;
    const int h = t >> 3;
    const float4 w0 = *(const float4*)(w + t * 8);
    const float4 w1 = *(const float4*)(w + t * 8 + 4);

    const float y0 = v0.x * norm * w0.x, y1 = v0.y * norm * w0.y;
    const float y2 = v0.z * norm * w0.z, y3 = v0.w * norm * w0.w;
    const float y4 = v1.x * norm * w1.x, y5 = v1.y * norm * w1.y;
    const float y6 = v1.z * norm * w1.z, y7 = v1.w * norm * w1.w;

    uint32_t* dst = dstbuf + (((size_t)b * NHEAD + h) * SEQ + srow) * 64
                  + (t & 7) * 8;
    uint4 o0, o1;
    o0.x = f2tf32(y0); o0.y = f2tf32(y4);
    o0.z = f2tf32(y1); o0.w = f2tf32(y5);
    o1.x = f2tf32(y2); o1.y = f2tf32(y6);
    o1.z = f2tf32(y3); o1.w = f2tf32(y7);
    *(uint4*)(dst)     = o0;
    *(uint4*)(dst + 4) = o1;
}

// ---------------------------------------------------------------------------
// Prepack V: transpose to [b][h][hd][key-perm], tf32.
// ---------------------------------------------------------------------------
__global__ __launch_bounds__(256) void prepack_v_kernel(
    const float* __restrict__ vin, uint32_t* __restrict__ vt)
{
    __shared__ float ts[64][65];
    const int t  = threadIdx.x;
    const int k0 = blockIdx.x * 64;
    const int h  = blockIdx.y;
    const int b  = blockIdx.z;

    for (int i = t; i < 64 * 16; i += 256) {
        const int r  = i >> 4;
        const int c4 = i & 15;
        const float4 vv = *(const float4*)(
            vin + ((size_t)b * SEQ + k0 + r) * DIM + h * HDIM + c4 * 4);
        ts[r][c4 * 4 + 0] = vv.x;
        ts[r][c4 * 4 + 1] = vv.y;
        ts[r][c4 * 4 + 2] = vv.z;
        ts[r][c4 * 4 + 3] = vv.w;
    }
    __syncthreads();

    const int hd = t >> 2;
    uint32_t* dst = vt + (((size_t)b * NHEAD + h) * 64 + hd) * SEQ + k0;
#pragma unroll
    for (int g2 = 0; g2 < 2; g2++) {
        const int g = (t & 3) * 2 + g2;
        uint4 w0, w1;
        w0.x = f2tf32(ts[g * 8 + 0][hd]); w0.y = f2tf32(ts[g * 8 + 4][hd]);
        w0.z = f2tf32(ts[g * 8 + 1][hd]); w0.w = f2tf32(ts[g * 8 + 5][hd]);
        w1.x = f2tf32(ts[g * 8 + 2][hd]); w1.y = f2tf32(ts[g * 8 + 6][hd]);
        w1.z = f2tf32(ts[g * 8 + 3][hd]); w1.w = f2tf32(ts[g * 8 + 7][hd]);
        *(uint4*)(dst + g * 8)     = w0;
        *(uint4*)(dst + g * 8 + 4) = w1;
    }
}

// ---------------------------------------------------------------------------
// Tensor-core flash attention v5 (R11 EXACT, measured best): static-max
// softmax, hoisted cp.async addressing, split-commit K/V, packed epilogue.
// ---------------------------------------------------------------------------
#define ASTR 72
#define SMAX 20.0f

__global__ __launch_bounds__(128, 4) void attn_tc_kernel(
    const uint32_t* __restrict__ qp, const uint32_t* __restrict__ kp,
    const uint32_t* __restrict__ vt, uint32_t* __restrict__ outp)
{
    extern __shared__ uint32_t sm[];
    uint32_t* Qs = sm;
    uint32_t* Ks = sm + 64 * ASTR;
    uint32_t* Vs = sm + 128 * ASTR;

    const int tid  = threadIdx.x;
    const int warp = tid >> 5;
    const int lane = tid & 31;
    const int gr   = lane >> 2;
    const int tg   = lane & 3;
    const int h    = blockIdx.y;
    const int b    = blockIdx.z;

    const int qrow0 = blockIdx.x * 64;
    const size_t bh = (size_t)b * NHEAD + h;
    const uint32_t* qbase = qp + (bh * SEQ + qrow0) * 64;

    const uint32_t qs_a = (uint32_t)__cvta_generic_to_shared(Qs);
    const uint32_t ks_a = (uint32_t)__cvta_generic_to_shared(Ks);
    const uint32_t vs_a = (uint32_t)__cvta_generic_to_shared(Vs);

    const int rr = tid >> 4;
    const int cc = (tid & 15) * 4;
    const uint32_t ksd = ks_a + (rr * ASTR + cc) * 4;
    const uint32_t vsd = vs_a + (rr * ASTR + cc) * 4;
    const uint32_t* kg = kp + bh * SEQ * 64 + rr * 64 + cc;
    const uint32_t* vg = vt + bh * 64 * SEQ + (size_t)rr * SEQ + cc;

#pragma unroll
    for (int n = 0; n < 8; n++)
        cp_async16(qs_a + ((rr + 8 * n) * ASTR + cc) * 4,
                   qbase + (rr + 8 * n) * 64 + cc);

    const int qr = warp * 16 + gr;

    float of[8][4];
#pragma unroll
    for (int nt = 0; nt < 8; nt++)
#pragma unroll
        for (int c = 0; c < 4; c++) of[nt][c] = 0.f;

    float l0 = 0.f, l1 = 0.f;

    for (int k0 = 0; k0 < SEQ; k0 += 64) {
        __syncthreads();

#pragma unroll
        for (int n = 0; n < 8; n++)
            cp_async16(ksd + n * (8 * ASTR * 4), kg + n * (8 * 64));
        cp_commit();
#pragma unroll
        for (int n = 0; n < 8; n++)
            cp_async16(vsd + n * (8 * ASTR * 4), vg + n * (8 * SEQ));
        cp_commit();
        kg += 64 * 64;
        vg += 64;

        asm volatile("cp.async.wait_group 1;\n" ::: "memory");
        __syncthreads();

        float sacc[8][4];
#pragma unroll
        for (int nt = 0; nt < 8; nt++)
#pragma unroll
            for (int c = 0; c < 4; c++) sacc[nt][c] = 0.f;

#pragma unroll
        for (int j = 0; j < 8; j++) {
            const uint2 q0 = *(const uint2*)&Qs[qr * ASTR + 8 * j + 2 * tg];
            const uint2 q1 = *(const uint2*)&Qs[(qr + 8) * ASTR + 8 * j + 2 * tg];
            uint32_t a[4] = {q0.x, q1.x, q0.y, q1.y};
#pragma unroll
            for (int nt = 0; nt < 8; nt++) {
                const uint2 kb = *(const uint2*)&Ks[(8 * nt + gr) * ASTR + 8 * j + 2 * tg];
                mma_tf32(sacc[nt], a, (const uint32_t*)&kb, sacc[nt]);
            }
        }

        asm volatile("cp.async.wait_group 0;\n" ::: "memory");
        __syncthreads();

#pragma unroll
        for (int j = 0; j < 8; j++) {
            uint32_t a[4];
            a[0] = f2tf32(ex2(sacc[j][0] - SMAX));
            a[1] = f2tf32(ex2(sacc[j][2] - SMAX));
            a[2] = f2tf32(ex2(sacc[j][1] - SMAX));
            a[3] = f2tf32(ex2(sacc[j][3] - SMAX));
            l0 += __uint_as_float(a[0]) + __uint_as_float(a[2]);
            l1 += __uint_as_float(a[1]) + __uint_as_float(a[3]);
#pragma unroll
            for (int nt = 0; nt < 8; nt++) {
                const uint2 vb = *(const uint2*)&Vs[(8 * nt + gr) * ASTR + 8 * j + 2 * tg];
                mma_tf32(of[nt], a, (const uint32_t*)&vb, of[nt]);
            }
        }
    }

    l0 += __shfl_xor_sync(0xFFFFFFFFu, l0, 1);
    l0 += __shfl_xor_sync(0xFFFFFFFFu, l0, 2);
    l1 += __shfl_xor_sync(0xFFFFFFFFu, l1, 1);
    l1 += __shfl_xor_sync(0xFFFFFFFFu, l1, 2);
    const float inv0 = 1.f / l0;
    const float inv1 = 1.f / l1;

    const int pe = perm8(2 * tg);
    const int po = perm8(2 * tg + 1);
    uint32_t* o0 = outp + ((size_t)b * SEQ + qrow0 + qr) * DIM + h * HDIM;
    uint32_t* o1 = o0 + 8 * DIM;
#pragma unroll
    for (int nt = 0; nt < 8; nt++) {
        o0[8 * nt + pe] = f2tf32(of[nt][0] * inv0);
        o0[8 * nt + po] = f2tf32(of[nt][1] * inv0);
        o1[8 * nt + pe] = f2tf32(of[nt][2] * inv1);
        o1[8 * nt + po] = f2tf32(of[nt][3] * inv1);
    }
}

// ---------------------------------------------------------------------------
// Launch
// ---------------------------------------------------------------------------
extern "C" void kernel_launch(void* const* d_in, const int* in_sizes, int n_in,
                              void* d_out, int out_size)
{
    const float* x   = (const float*)d_in[0];
    const float* Wq  = (const float*)d_in[1];
    const float* bq  = (const float*)d_in[2];
    const float* Wk  = (const float*)d_in[3];
    const float* bk  = (const float*)d_in[4];
    const float* Wv  = (const float*)d_in[5];
    const float* bv  = (const float*)d_in[6];
    const float* Wo  = (const float*)d_in[7];
    const float* bo  = (const float*)d_in[8];
    const float* nqw = (const float*)d_in[9];
    const float* nkw = (const float*)d_in[10];
    float* out = (float*)d_out;

    float *dq, *dk, *dv;
    uint32_t *dqp, *dkp, *dvt, *dxp, *dwp, *dap;
    cudaGetSymbolAddress((void**)&dq,  g_q);
    cudaGetSymbolAddress((void**)&dk,  g_k);
    cudaGetSymbolAddress((void**)&dv,  g_v);
    cudaGetSymbolAddress((void**)&dqp, g_qp);
    cudaGetSymbolAddress((void**)&dkp, g_kp);
    cudaGetSymbolAddress((void**)&dvt, g_vt);
    cudaGetSymbolAddress((void**)&dxp, g_xp);
    cudaGetSymbolAddress((void**)&dwp, g_wp);
    cudaGetSymbolAddress((void**)&dap, g_ap);

    const int gemm_smem = 3 * 192 * G2STR * 4;      // 55296 bytes
    cudaFuncSetAttribute(gemm_s4_kernel,
                         cudaFuncAttributeMaxDynamicSharedMemorySize, gemm_smem);
    cudaFuncSetAttribute(gemm_s4_qkv_kernel,
                         cudaFuncAttributeMaxDynamicSharedMemorySize, gemm_smem);
    const int attn_smem = 3 * 64 * ASTR * 4;        // 55296 bytes
    cudaFuncSetAttribute(attn_tc_kernel,
                         cudaFuncAttributeMaxDynamicSharedMemorySize, attn_smem);

    pack_tf32_kernel<<<MROWS / 2, 256>>>(x, dxp);
    dim3 wgrid(DIM / 2, 4);
    pack_w4_kernel<<<wgrid, 256>>>(Wq, Wk, Wv, Wo, dwp);

    dim3 qkvgrid(DIM / 64, MROWS / 128, 3);   // (16, 32, 3)
    gemm_s4_qkv_kernel<<<qkvgrid, 128, gemm_smem>>>(
        dxp, dwp, bq, bk, bv, dq, dk, dv);

    dim3 pgrid(MROWS, 2);
    prepack_qk_kernel<<<pgrid, 128>>>(dq, dk, nqw, nkw, dqp, dkp);
    dim3 vgrid(SEQ / 64, NHEAD, BATCH);
    prepack_v_kernel<<<vgrid, 256>>>(dv, dvt);

    dim3 agrid(SEQ / 64, NHEAD, BATCH);
    attn_tc_kernel<<<agrid, 128, attn_smem>>>(dqp, dkp, dvt, dap);

    dim3 ggrid(DIM / 64, MROWS / 128);        // (16, 32)
    gemm_s4_kernel<<<ggrid, 128, gemm_smem>>>(
        dap, dwp + 3 * (size_t)DIM * DIM, bo, out);
}

// round 15
// speedup vs baseline: 1.3990x; 1.0304x over previous
#include <cuda_runtime.h>
#include <cuda_bf16.h>
#include <math.h>
#include <stdint.h>

// Problem constants
#define BATCH 2
#define SEQ   2048
#define DIM   1024
#define NHEAD 16
#define HDIM  64
#define MROWS (BATCH*SEQ)   // 4096

// Scratch buffers (allocation-free rule: static device globals)
__device__ float    g_q[MROWS * DIM];
__device__ float    g_k[MROWS * DIM];
__device__ uint32_t g_qp[MROWS * DIM];      // tf32 packed Q [b][h][s][hdperm]
__device__ uint32_t g_kp[MROWS * DIM];      // tf32 packed K [b][h][sperm][hdperm]
__device__ uint32_t g_vt[MROWS * DIM];      // tf32 packed V [b][h][hd][keyperm]
__device__ uint32_t g_xp[MROWS * DIM];      // tf32 packed X (k-perm)
__device__ uint32_t g_wp[4 * DIM * DIM];    // tf32 packed Wq,Wk,Wv,Wo (k-perm)
__device__ uint32_t g_ap[MROWS * DIM];      // tf32 packed attn-out (k-perm)

__device__ __forceinline__ uint32_t f2tf32(float f) {
    uint32_t u;
    asm("cvt.rna.tf32.f32 %0, %1;" : "=r"(u) : "f"(f));
    return u;
}

__device__ __forceinline__ float ex2(float x) {
    float y;
    asm("ex2.approx.f32 %0, %1;" : "=f"(y) : "f"(x));
    return y;
}

__device__ __forceinline__ void mma_tf32(float* d, const uint32_t* a,
                                         const uint32_t* b, const float* c) {
    asm volatile(
        "mma.sync.aligned.m16n8k8.row.col.f32.tf32.tf32.f32 "
        "{%0,%1,%2,%3}, {%4,%5,%6,%7}, {%8,%9}, {%10,%11,%12,%13};\n"
        : "=f"(d[0]), "=f"(d[1]), "=f"(d[2]), "=f"(d[3])
        : "r"(a[0]), "r"(a[1]), "r"(a[2]), "r"(a[3]),
          "r"(b[0]), "r"(b[1]),
          "f"(c[0]), "f"(c[1]), "f"(c[2]), "f"(c[3]));
}

__device__ __forceinline__ void cp_async16(uint32_t sm_addr, const void* gptr) {
    asm volatile("cp.async.cg.shared.global [%0], [%1], 16;\n"
                 :: "r"(sm_addr), "l"(gptr));
}
__device__ __forceinline__ void cp_commit() {
    asm volatile("cp.async.commit_group;\n" ::: "memory");
}

// perm within groups of 8: logical l -> 2*(l%4) + (l/4)
__device__ __forceinline__ int perm8(int l) {
    return (l & ~7) | (2 * (l & 3)) | ((l >> 2) & 1);
}

// ---------------------------------------------------------------------------
// Fused pack: X (rows 0..MROWS) and the 4 weight matrices -> tf32, perm8 on k.
// Grid: MROWS/2 + 4*DIM/2 = 4096 blocks, 256 thr, 2 rows/block.
// ---------------------------------------------------------------------------
__global__ __launch_bounds__(256) void pack_all_kernel(
    const float* __restrict__ x,
    const float* __restrict__ Wq, const float* __restrict__ Wk,
    const float* __restrict__ Wv, const float* __restrict__ Wo,
    uint32_t* __restrict__ xp, uint32_t* __restrict__ wp)
{
    const int bx = blockIdx.x;
    const float* src;
    uint32_t* dst;
    int local;
    if (bx < MROWS / 2) {
        src = x; dst = xp; local = bx;
    } else {
        const int i = bx - MROWS / 2;
        const int w = i / (DIM / 2);
        local = i % (DIM / 2);
        switch (w) {
            case 0: src = Wq; break;
            case 1: src = Wk; break;
            case 2: src = Wv; break;
            default: src = Wo; break;
        }
        dst = wp + (size_t)w * DIM * DIM;
    }
    const int t = threadIdx.x;
    const size_t base = ((size_t)local * 2 + (t >> 7)) * DIM + (t & 127) * 8;
    const float4 v0 = *(const float4*)(src + base);
    const float4 v1 = *(const float4*)(src + base + 4);
    uint4 o0, o1;
    o0.x = f2tf32(v0.x); o0.y = f2tf32(v1.x);
    o0.z = f2tf32(v0.y); o0.w = f2tf32(v1.y);
    o1.x = f2tf32(v0.z); o1.y = f2tf32(v1.z);
    o1.z = f2tf32(v0.w); o1.w = f2tf32(v1.w);
    *(uint4*)(dst + base)     = o0;
    *(uint4*)(dst + base + 4) = o1;
}

// ---------------------------------------------------------------------------
// Packed tf32 GEMM v3 (R13/R14-frozen): 128-thr blocks, 4 blocks/SM, tile
// 128x64, k-tile 16, 3-stage cp.async, ONE barrier per k-tile.
// vmode=1: V-projection epilogue writes TRANSPOSED key-permuted tf32 Vt
// directly (value-identical to the old prepack_v path).
// ---------------------------------------------------------------------------
#define G2STR 24
#define G2NKT (DIM / 16)   // 64 k-tiles

__device__ __forceinline__ void gemm_s4_body(
    const uint32_t* __restrict__ A, const uint32_t* __restrict__ W,
    const float* __restrict__ bias, float* __restrict__ C,
    uint32_t* __restrict__ vtout, int vmode,
    int bx, int by, uint32_t* gsm)
{
    const int tid  = threadIdx.x;
    const int bm   = by * 128;
    const int bn   = bx * 64;
    const int warp = tid >> 5;
    const int lane = tid & 31;
    const int wm   = (warp >> 1) * 64;    // 0 or 64
    const int wn   = (warp & 1) * 32;     // 0 or 32
    const int gr   = lane >> 2;
    const int tg   = lane & 3;

    const uint32_t sm_a = (uint32_t)__cvta_generic_to_shared(gsm);

    const int r0 = tid >> 2;
    const int cw = (tid & 3) * 4;
    const uint32_t* arow = A + (size_t)(bm + r0) * DIM + cw;
    const uint32_t* wrow = W + (size_t)(bn + r0) * DIM + cw;

    float acc[4][4][4];
#pragma unroll
    for (int i = 0; i < 4; i++)
#pragma unroll
        for (int j = 0; j < 4; j++)
#pragma unroll
            for (int c = 0; c < 4; c++) acc[i][j][c] = 0.f;

    auto issue = [&](int t, int st) {
        const uint32_t base = sm_a + st * (192 * G2STR * 4);
        const uint32_t* ag = arow + t * 16;
        const uint32_t* wg = wrow + t * 16;
#pragma unroll
        for (int n = 0; n < 4; n++)
            cp_async16(base + ((r0 + 32 * n) * G2STR + cw) * 4,
                       ag + (size_t)(32 * n) * DIM);
#pragma unroll
        for (int n = 0; n < 2; n++)
            cp_async16(base + ((128 + r0 + 32 * n) * G2STR + cw) * 4,
                       wg + (size_t)(32 * n) * DIM);
        cp_commit();
    };

    issue(0, 0);
    issue(1, 1);

    int st_c = 0;
    int st_i = 2;
    for (int t = 0; t < G2NKT; t++) {
        asm volatile("cp.async.wait_group 1;\n" ::: "memory");
        __syncthreads();
        if (t + 2 < G2NKT) issue(t + 2, st_i);

        const uint32_t* Ab = gsm + st_c * 192 * G2STR;
        const uint32_t* Bb = Ab + 128 * G2STR;

#pragma unroll
        for (int ks = 0; ks < 2; ks++) {
            const int kk = ks * 8;
            uint32_t af[4][4], bf[4][2];
#pragma unroll
            for (int i = 0; i < 4; i++) {
                const int r = wm + i * 16 + gr;
                const uint2 a02 = *(const uint2*)&Ab[r * G2STR + kk + 2 * tg];
                const uint2 a13 = *(const uint2*)&Ab[(r + 8) * G2STR + kk + 2 * tg];
                af[i][0] = a02.x; af[i][1] = a13.x;
                af[i][2] = a02.y; af[i][3] = a13.y;
            }
#pragma unroll
            for (int j = 0; j < 4; j++) {
                const int n = wn + j * 8 + gr;
                const uint2 bb = *(const uint2*)&Bb[n * G2STR + kk + 2 * tg];
                bf[j][0] = bb.x; bf[j][1] = bb.y;
            }
#pragma unroll
            for (int i = 0; i < 4; i++)
#pragma unroll
                for (int j = 0; j < 4; j++)
                    mma_tf32(acc[i][j], af[i], bf[j], acc[i][j]);
        }

        st_c = (st_c == 2) ? 0 : st_c + 1;
        st_i = (st_i == 2) ? 0 : st_i + 1;
    }

    if (!vmode) {
#pragma unroll
        for (int i = 0; i < 4; i++) {
#pragma unroll
            for (int j = 0; j < 4; j++) {
                const int row = bm + wm + i * 16 + gr;
                const int col = bn + wn + j * 8 + 2 * tg;
                const float2 b01 = *(const float2*)(bias + col);
                float2 o0, o1;
                o0.x = acc[i][j][0] + b01.x;
                o0.y = acc[i][j][1] + b01.y;
                o1.x = acc[i][j][2] + b01.x;
                o1.y = acc[i][j][3] + b01.y;
                *(float2*)(C + (size_t)row * DIM + col)       = o0;
                *(float2*)(C + (size_t)(row + 8) * DIM + col) = o1;
            }
        }
    } else {
        // transposed tf32 store: Vt[(b*16+h)*64+hd][key-perm]
#pragma unroll
        for (int i = 0; i < 4; i++) {
#pragma unroll
            for (int j = 0; j < 4; j++) {
                const int row = bm + wm + i * 16 + gr;     // token global
                const int col = bn + wn + j * 8 + 2 * tg;  // hd global
                const float2 b01 = *(const float2*)(bias + col);
                const int bb  = row >> 11;
                const int tok = row & 2047;
                const int pt  = perm8(tok);
                const int h   = col >> 6;
                const int hd  = col & 63;
                uint32_t* base = vtout
                    + (((size_t)bb * NHEAD + h) * 64 + hd) * SEQ;
                base[pt]           = f2tf32(acc[i][j][0] + b01.x);
                base[SEQ + pt]     = f2tf32(acc[i][j][1] + b01.y);
                base[pt + 8]       = f2tf32(acc[i][j][2] + b01.x);
                base[SEQ + pt + 8] = f2tf32(acc[i][j][3] + b01.y);
            }
        }
    }
}

__global__ __launch_bounds__(128, 4) void gemm_s4_kernel(
    const uint32_t* __restrict__ A, const uint32_t* __restrict__ W,
    const float* __restrict__ bias, float* __restrict__ C)
{
    extern __shared__ uint32_t gsm[];
    gemm_s4_body(A, W, bias, C, nullptr, 0, blockIdx.x, blockIdx.y, gsm);
}

__global__ __launch_bounds__(128, 4) void gemm_s4_qkv_kernel(
    const uint32_t* __restrict__ A, const uint32_t* __restrict__ Wp,
    const float* __restrict__ bq, const float* __restrict__ bk,
    const float* __restrict__ bv,
    float* __restrict__ Cq, float* __restrict__ Ck,
    uint32_t* __restrict__ vt)
{
    extern __shared__ uint32_t gsm[];
    const float* b; float* C; int vmode;
    if (blockIdx.z == 0)      { b = bq; C = Cq;      vmode = 0; }
    else if (blockIdx.z == 1) { b = bk; C = Ck;      vmode = 0; }
    else                      { b = bv; C = nullptr; vmode = 1; }
    gemm_s4_body(A, Wp + (size_t)blockIdx.z * DIM * DIM, b, C, vt, vmode,
                 blockIdx.x, blockIdx.y, gsm);
}

// ---------------------------------------------------------------------------
// Prepack Q/K: fused RMSNorm + tf32 + head split + perm, vectorized stores.
// ---------------------------------------------------------------------------
__global__ __launch_bounds__(128) void prepack_qk_kernel(
    const float* __restrict__ qin, const float* __restrict__ kin,
    const float* __restrict__ nqw, const float* __restrict__ nkw,
    uint32_t* __restrict__ qp, uint32_t* __restrict__ kp)
{
    const int row = blockIdx.x;
    const int isk = blockIdx.y;
    const float* src = (isk ? kin : qin) + (size_t)row * DIM;
    const float* w   = isk ? nkw : nqw;
    uint32_t* dstbuf = isk ? kp : qp;
    const int t = threadIdx.x;

    const float4 v0 = *(const float4*)(src + t * 8);
    const float4 v1 = *(const float4*)(src + t * 8 + 4);
    float ss = v0.x * v0.x + v0.y * v0.y + v0.z * v0.z + v0.w * v0.w
             + v1.x * v1.x + v1.y * v1.y + v1.z * v1.z + v1.w * v1.w;
#pragma unroll
    for (int off = 16; off > 0; off >>= 1)
        ss += __shfl_xor_sync(0xFFFFFFFFu, ss, off);
    __shared__ float red[4];
    if ((t & 31) == 0) red[t >> 5] = ss;
    __syncthreads();
    const float total = red[0] + red[1] + red[2] + red[3];

    const float SCALE = 0.125f * 1.4426950408889634f;
    float norm = rsqrtf(total * (1.0f / DIM) + 1e-6f);
    if (!isk) norm *= SCALE;

    const int b = row >> 11;
    const int s = row & 2047;
    const int srow = isk ? perm8(s) : s;
    const int h = t >> 3;
    const float4 w0 = *(const float4*)(w + t * 8);
    const float4 w1 = *(const float4*)(w + t * 8 + 4);

    const float y0 = v0.x * norm * w0.x, y1 = v0.y * norm * w0.y;
    const float y2 = v0.z * norm * w0.z, y3 = v0.w * norm * w0.w;
    const float y4 = v1.x * norm * w1.x, y5 = v1.y * norm * w1.y;
    const float y6 = v1.z * norm * w1.z, y7 = v1.w * norm * w1.w;

    uint32_t* dst = dstbuf + (((size_t)b * NHEAD + h) * SEQ + srow) * 64
                  + (t & 7) * 8;
    uint4 o0, o1;
    o0.x = f2tf32(y0); o0.y = f2tf32(y4);
    o0.z = f2tf32(y1); o0.w = f2tf32(y5);
    o1.x = f2tf32(y2); o1.y = f2tf32(y6);
    o1.z = f2tf32(y3); o1.w = f2tf32(y7);
    *(uint4*)(dst)     = o0;
    *(uint4*)(dst + 4) = o1;
}

// ---------------------------------------------------------------------------
// Tensor-core flash attention v7 = R11 + K-prefetch pipeline:
//   per tile: sync; issue V(t); wait_group 1 (K(t) done, V pending); sync;
//   S(t); wait_group 0 (V done); sync; issue K(t+1); PV(t).
// K(t+1) streams in UNDER the PV phase; single K buffer is safe because the
// post-S barrier drains all K readers before the issue. cp.async groups
// retire in commit order, so wait_group 1 with {K,V} pending = K complete.
// Static-max softmax, hoisted addressing, packed epilogue (all R11-frozen).
// ---------------------------------------------------------------------------
#define ASTR 72
#define SMAX 20.0f

__global__ __launch_bounds__(128, 4) void attn_tc_kernel(
    const uint32_t* __restrict__ qp, const uint32_t* __restrict__ kp,
    const uint32_t* __restrict__ vt, uint32_t* __restrict__ outp)
{
    extern __shared__ uint32_t sm[];
    uint32_t* Qs = sm;
    uint32_t* Ks = sm + 64 * ASTR;
    uint32_t* Vs = sm + 128 * ASTR;

    const int tid  = threadIdx.x;
    const int warp = tid >> 5;
    const int lane = tid & 31;
    const int gr   = lane >> 2;
    const int tg   = lane & 3;
    const int h    = blockIdx.y;
    const int b    = blockIdx.z;

    const int qrow0 = blockIdx.x * 64;
    const size_t bh = (size_t)b * NHEAD + h;
    const uint32_t* qbase = qp + (bh * SEQ + qrow0) * 64;

    const uint32_t qs_a = (uint32_t)__cvta_generic_to_shared(Qs);
    const uint32_t ks_a = (uint32_t)__cvta_generic_to_shared(Ks);
    const uint32_t vs_a = (uint32_t)__cvta_generic_to_shared(Vs);

    const int rr = tid >> 4;
    const int cc = (tid & 15) * 4;
    const uint32_t ksd = ks_a + (rr * ASTR + cc) * 4;
    const uint32_t vsd = vs_a + (rr * ASTR + cc) * 4;
    const uint32_t* kg = kp + bh * SEQ * 64 + rr * 64 + cc;
    const uint32_t* vg = vt + bh * 64 * SEQ + (size_t)rr * SEQ + cc;

    // prologue group: Q (64 rows) + K(0)
#pragma unroll
    for (int n = 0; n < 8; n++)
        cp_async16(qs_a + ((rr + 8 * n) * ASTR + cc) * 4,
                   qbase + (rr + 8 * n) * 64 + cc);
#pragma unroll
    for (int n = 0; n < 8; n++)
        cp_async16(ksd + n * (8 * ASTR * 4), kg + n * (8 * 64));
    cp_commit();
    kg += 64 * 64;

    const int qr = warp * 16 + gr;

    float of[8][4];
#pragma unroll
    for (int nt = 0; nt < 8; nt++)
#pragma unroll
        for (int c = 0; c < 4; c++) of[nt][c] = 0.f;

    float l0 = 0.f, l1 = 0.f;

    for (int k0 = 0; k0 < SEQ; k0 += 64) {
        __syncthreads();   // PV(t-1) readers done (V buffer free)

        // issue V(t)
#pragma unroll
        for (int n = 0; n < 8; n++)
            cp_async16(vsd + n * (8 * ASTR * 4), vg + n * (8 * SEQ));
        cp_commit();
        vg += 64;

        // K(t) done (V(t) may still be in flight)
        asm volatile("cp.async.wait_group 1;\n" ::: "memory");
        __syncthreads();

        // S = Q @ K^T — V(t) streams in underneath
        float sacc[8][4];
#pragma unroll
        for (int nt = 0; nt < 8; nt++)
#pragma unroll
            for (int c = 0; c < 4; c++) sacc[nt][c] = 0.f;

#pragma unroll
        for (int j = 0; j < 8; j++) {
            const uint2 q0 = *(const uint2*)&Qs[qr * ASTR + 8 * j + 2 * tg];
            const uint2 q1 = *(const uint2*)&Qs[(qr + 8) * ASTR + 8 * j + 2 * tg];
            uint32_t a[4] = {q0.x, q1.x, q0.y, q1.y};
#pragma unroll
            for (int nt = 0; nt < 8; nt++) {
                const uint2 kb = *(const uint2*)&Ks[(8 * nt + gr) * ASTR + 8 * j + 2 * tg];
                mma_tf32(sacc[nt], a, (const uint32_t*)&kb, sacc[nt]);
            }
        }

        // V(t) ready; all warps past S -> K buffer free for K(t+1)
        asm volatile("cp.async.wait_group 0;\n" ::: "memory");
        __syncthreads();

        if (k0 + 64 < SEQ) {
#pragma unroll
            for (int n = 0; n < 8; n++)
                cp_async16(ksd + n * (8 * ASTR * 4), kg + n * (8 * 64));
            cp_commit();
            kg += 64 * 64;
        }

        // P = exp2(S - SMAX); O += P @ V  (K(t+1) streams in underneath)
#pragma unroll
        for (int j = 0; j < 8; j++) {
            uint32_t a[4];
            a[0] = f2tf32(ex2(sacc[j][0] - SMAX));
            a[1] = f2tf32(ex2(sacc[j][2] - SMAX));
            a[2] = f2tf32(ex2(sacc[j][1] - SMAX));
            a[3] = f2tf32(ex2(sacc[j][3] - SMAX));
            l0 += __uint_as_float(a[0]) + __uint_as_float(a[2]);
            l1 += __uint_as_float(a[1]) + __uint_as_float(a[3]);
#pragma unroll
            for (int nt = 0; nt < 8; nt++) {
                const uint2 vb = *(const uint2*)&Vs[(8 * nt + gr) * ASTR + 8 * j + 2 * tg];
                mma_tf32(of[nt], a, (const uint32_t*)&vb, of[nt]);
            }
        }
    }

    l0 += __shfl_xor_sync(0xFFFFFFFFu, l0, 1);
    l0 += __shfl_xor_sync(0xFFFFFFFFu, l0, 2);
    l1 += __shfl_xor_sync(0xFFFFFFFFu, l1, 1);
    l1 += __shfl_xor_sync(0xFFFFFFFFu, l1, 2);
    const float inv0 = 1.f / l0;
    const float inv1 = 1.f / l1;

    const int pe = perm8(2 * tg);
    const int po = perm8(2 * tg + 1);
    uint32_t* o0 = outp + ((size_t)b * SEQ + qrow0 + qr) * DIM + h * HDIM;
    uint32_t* o1 = o0 + 8 * DIM;
#pragma unroll
    for (int nt = 0; nt < 8; nt++) {
        o0[8 * nt + pe] = f2tf32(of[nt][0] * inv0);
        o0[8 * nt + po] = f2tf32(of[nt][1] * inv0);
        o1[8 * nt + pe] = f2tf32(of[nt][2] * inv1);
        o1[8 * nt + po] = f2tf32(of[nt][3] * inv1);
    }
}

// ---------------------------------------------------------------------------
// Launch
// ---------------------------------------------------------------------------
extern "C" void kernel_launch(void* const* d_in, const int* in_sizes, int n_in,
                              void* d_out, int out_size)
{
    const float* x   = (const float*)d_in[0];
    const float* Wq  = (const float*)d_in[1];
    const float* bq  = (const float*)d_in[2];
    const float* Wk  = (const float*)d_in[3];
    const float* bk  = (const float*)d_in[4];
    const float* Wv  = (const float*)d_in[5];
    const float* bv  = (const float*)d_in[6];
    const float* Wo  = (const float*)d_in[7];
    const float* bo  = (const float*)d_in[8];
    const float* nqw = (const float*)d_in[9];
    const float* nkw = (const float*)d_in[10];
    float* out = (float*)d_out;

    float *dq, *dk;
    uint32_t *dqp, *dkp, *dvt, *dxp, *dwp, *dap;
    cudaGetSymbolAddress((void**)&dq,  g_q);
    cudaGetSymbolAddress((void**)&dk,  g_k);
    cudaGetSymbolAddress((void**)&dqp, g_qp);
    cudaGetSymbolAddress((void**)&dkp, g_kp);
    cudaGetSymbolAddress((void**)&dvt, g_vt);
    cudaGetSymbolAddress((void**)&dxp, g_xp);
    cudaGetSymbolAddress((void**)&dwp, g_wp);
    cudaGetSymbolAddress((void**)&dap, g_ap);

    const int gemm_smem = 3 * 192 * G2STR * 4;      // 55296 bytes
    cudaFuncSetAttribute(gemm_s4_kernel,
                         cudaFuncAttributeMaxDynamicSharedMemorySize, gemm_smem);
    cudaFuncSetAttribute(gemm_s4_qkv_kernel,
                         cudaFuncAttributeMaxDynamicSharedMemorySize, gemm_smem);
    const int attn_smem = 3 * 64 * ASTR * 4;        // 55296 bytes
    cudaFuncSetAttribute(attn_tc_kernel,
                         cudaFuncAttributeMaxDynamicSharedMemorySize, attn_smem);

    pack_all_kernel<<<MROWS / 2 + 2 * DIM, 256>>>(x, Wq, Wk, Wv, Wo, dxp, dwp);

    dim3 qkvgrid(DIM / 64, MROWS / 128, 3);   // (16, 32, 3)
    gemm_s4_qkv_kernel<<<qkvgrid, 128, gemm_smem>>>(
        dxp, dwp, bq, bk, bv, dq, dk, dvt);

    dim3 pgrid(MROWS, 2);
    prepack_qk_kernel<<<pgrid, 128>>>(dq, dk, nqw, nkw, dqp, dkp);

    dim3 agrid(SEQ / 64, NHEAD, BATCH);
    attn_tc_kernel<<<agrid, 128, attn_smem>>>(dqp, dkp, dvt, dap);

    dim3 ggrid(DIM / 64, MROWS / 128);        // (16, 32)
    gemm_s4_kernel<<<ggrid, 128, gemm_smem>>>(
        dap, dwp + 3 * (size_t)DIM * DIM, bo, out);
}

// round 17
// speedup vs baseline: 1.5617x; 1.1163x over previous
#include <cuda_runtime.h>
#include <cuda_bf16.h>
#include <cuda_fp16.h>
#include <math.h>
#include <stdint.h>

// Problem constants
#define BATCH 2
#define SEQ   2048
#define DIM   1024
#define NHEAD 16
#define HDIM  64
#define MROWS (BATCH*SEQ)   // 4096

// Scratch buffers (allocation-free rule: static device globals)
__device__ float    g_q[MROWS * DIM];
__device__ float    g_k[MROWS * DIM];
__device__ uint32_t g_qp[MROWS * DIM];   // tf32 packed Q [b][h][s][hdperm]
__device__ uint32_t g_kp[MROWS * DIM];   // tf32 packed K [b][h][s][hdperm]
__device__ __half   g_vt[MROWS * DIM];   // fp16 packed V [b][h][hd][keyperm16]
__device__ uint32_t g_xp[MROWS * DIM];   // tf32 packed X (k-perm)
__device__ uint32_t g_wp[4 * DIM * DIM]; // tf32 packed Wq,Wk,Wv,Wo (k-perm)
__device__ uint32_t g_ap[MROWS * DIM];   // tf32 packed attn-out (k-perm)

__device__ __forceinline__ uint32_t f2tf32(float f) {
    uint32_t u;
    asm("cvt.rna.tf32.f32 %0, %1;" : "=r"(u) : "f"(f));
    return u;
}

__device__ __forceinline__ float ex2(float x) {
    float y;
    asm("ex2.approx.f32 %0, %1;" : "=f"(y) : "f"(x));
    return y;
}

__device__ __forceinline__ uint32_t pk_f16x2(float hi, float lo) {
    uint32_t r;
    asm("cvt.rn.f16x2.f32 %0, %1, %2;" : "=r"(r) : "f"(hi), "f"(lo));
    return r;
}

__device__ __forceinline__ void mma_tf32(float* d, const uint32_t* a,
                                         const uint32_t* b, const float* c) {
    asm volatile(
        "mma.sync.aligned.m16n8k8.row.col.f32.tf32.tf32.f32 "
        "{%0,%1,%2,%3}, {%4,%5,%6,%7}, {%8,%9}, {%10,%11,%12,%13};\n"
        : "=f"(d[0]), "=f"(d[1]), "=f"(d[2]), "=f"(d[3])
        : "r"(a[0]), "r"(a[1]), "r"(a[2]), "r"(a[3]),
          "r"(b[0]), "r"(b[1]),
          "f"(c[0]), "f"(c[1]), "f"(c[2]), "f"(c[3]));
}

__device__ __forceinline__ void mma_f16(float* d, const uint32_t* a,
                                        const uint32_t* b, const float* c) {
    asm volatile(
        "mma.sync.aligned.m16n8k16.row.col.f32.f16.f16.f32 "
        "{%0,%1,%2,%3}, {%4,%5,%6,%7}, {%8,%9}, {%10,%11,%12,%13};\n"
        : "=f"(d[0]), "=f"(d[1]), "=f"(d[2]), "=f"(d[3])
        : "r"(a[0]), "r"(a[1]), "r"(a[2]), "r"(a[3]),
          "r"(b[0]), "r"(b[1]),
          "f"(c[0]), "f"(c[1]), "f"(c[2]), "f"(c[3]));
}

__device__ __forceinline__ void cp_async16(uint32_t sm_addr, const void* gptr) {
    asm volatile("cp.async.cg.shared.global [%0], [%1], 16;\n"
                 :: "r"(sm_addr), "l"(gptr));
}
__device__ __forceinline__ void cp_commit() {
    asm volatile("cp.async.commit_group;\n" ::: "memory");
}

// perm within groups of 8 (hd-axis packing): logical l -> 2*(l%4) + (l/4)
__device__ __forceinline__ int perm8(int l) {
    return (l & ~7) | (2 * (l & 3)) | ((l >> 2) & 1);
}
// perm within 16 (fp16 V key-axis): {2t,2t+1,2t+8,2t+9} -> contiguous quad t
__device__ __forceinline__ int vperm16(int k) {
    return ((k >> 1) & 3) * 4 + (k & 1) + ((k >> 3) & 1) * 2;
}

// ---------------------------------------------------------------------------
// Fused pack: X and the 4 weight matrices -> tf32, perm8 on k.
// ---------------------------------------------------------------------------
__global__ __launch_bounds__(256) void pack_all_kernel(
    const float* __restrict__ x,
    const float* __restrict__ Wq, const float* __restrict__ Wk,
    const float* __restrict__ Wv, const float* __restrict__ Wo,
    uint32_t* __restrict__ xp, uint32_t* __restrict__ wp)
{
    const int bx = blockIdx.x;
    const float* src;
    uint32_t* dst;
    int local;
    if (bx < MROWS / 2) {
        src = x; dst = xp; local = bx;
    } else {
        const int i = bx - MROWS / 2;
        const int w = i / (DIM / 2);
        local = i % (DIM / 2);
        switch (w) {
            case 0: src = Wq; break;
            case 1: src = Wk; break;
            case 2: src = Wv; break;
            default: src = Wo; break;
        }
        dst = wp + (size_t)w * DIM * DIM;
    }
    const int t = threadIdx.x;
    const size_t base = ((size_t)local * 2 + (t >> 7)) * DIM + (t & 127) * 8;
    const float4 v0 = *(const float4*)(src + base);
    const float4 v1 = *(const float4*)(src + base + 4);
    uint4 o0, o1;
    o0.x = f2tf32(v0.x); o0.y = f2tf32(v1.x);
    o0.z = f2tf32(v0.y); o0.w = f2tf32(v1.y);
    o1.x = f2tf32(v0.z); o1.y = f2tf32(v1.z);
    o1.z = f2tf32(v0.w); o1.w = f2tf32(v1.w);
    *(uint4*)(dst + base)     = o0;
    *(uint4*)(dst + base + 4) = o1;
}

// ---------------------------------------------------------------------------
// Packed tf32 GEMM v3 (R13/R14-frozen): 128-thr blocks, 4 blocks/SM, tile
// 128x64, k-tile 16, 3-stage cp.async, ONE barrier per k-tile.
// vmode=1: V-projection epilogue writes fp16 TRANSPOSED vperm16 Vt directly.
// ---------------------------------------------------------------------------
#define G2STR 24
#define G2NKT (DIM / 16)   // 64 k-tiles

__device__ __forceinline__ void gemm_s4_body(
    const uint32_t* __restrict__ A, const uint32_t* __restrict__ W,
    const float* __restrict__ bias, float* __restrict__ C,
    __half* __restrict__ vtout, int vmode,
    int bx, int by, uint32_t* gsm)
{
    const int tid  = threadIdx.x;
    const int bm   = by * 128;
    const int bn   = bx * 64;
    const int warp = tid >> 5;
    const int lane = tid & 31;
    const int wm   = (warp >> 1) * 64;
    const int wn   = (warp & 1) * 32;
    const int gr   = lane >> 2;
    const int tg   = lane & 3;

    const uint32_t sm_a = (uint32_t)__cvta_generic_to_shared(gsm);

    const int r0 = tid >> 2;
    const int cw = (tid & 3) * 4;
    const uint32_t* arow = A + (size_t)(bm + r0) * DIM + cw;
    const uint32_t* wrow = W + (size_t)(bn + r0) * DIM + cw;

    float acc[4][4][4];
#pragma unroll
    for (int i = 0; i < 4; i++)
#pragma unroll
        for (int j = 0; j < 4; j++)
#pragma unroll
            for (int c = 0; c < 4; c++) acc[i][j][c] = 0.f;

    auto issue = [&](int t, int st) {
        const uint32_t base = sm_a + st * (192 * G2STR * 4);
        const uint32_t* ag = arow + t * 16;
        const uint32_t* wg = wrow + t * 16;
#pragma unroll
        for (int n = 0; n < 4; n++)
            cp_async16(base + ((r0 + 32 * n) * G2STR + cw) * 4,
                       ag + (size_t)(32 * n) * DIM);
#pragma unroll
        for (int n = 0; n < 2; n++)
            cp_async16(base + ((128 + r0 + 32 * n) * G2STR + cw) * 4,
                       wg + (size_t)(32 * n) * DIM);
        cp_commit();
    };

    issue(0, 0);
    issue(1, 1);

    int st_c = 0;
    int st_i = 2;
    for (int t = 0; t < G2NKT; t++) {
        asm volatile("cp.async.wait_group 1;\n" ::: "memory");
        __syncthreads();
        if (t + 2 < G2NKT) issue(t + 2, st_i);

        const uint32_t* Ab = gsm + st_c * 192 * G2STR;
        const uint32_t* Bb = Ab + 128 * G2STR;

#pragma unroll
        for (int ks = 0; ks < 2; ks++) {
            const int kk = ks * 8;
            uint32_t af[4][4], bf[4][2];
#pragma unroll
            for (int i = 0; i < 4; i++) {
                const int r = wm + i * 16 + gr;
                const uint2 a02 = *(const uint2*)&Ab[r * G2STR + kk + 2 * tg];
                const uint2 a13 = *(const uint2*)&Ab[(r + 8) * G2STR + kk + 2 * tg];
                af[i][0] = a02.x; af[i][1] = a13.x;
                af[i][2] = a02.y; af[i][3] = a13.y;
            }
#pragma unroll
            for (int j = 0; j < 4; j++) {
                const int n = wn + j * 8 + gr;
                const uint2 bb = *(const uint2*)&Bb[n * G2STR + kk + 2 * tg];
                bf[j][0] = bb.x; bf[j][1] = bb.y;
            }
#pragma unroll
            for (int i = 0; i < 4; i++)
#pragma unroll
                for (int j = 0; j < 4; j++)
                    mma_tf32(acc[i][j], af[i], bf[j], acc[i][j]);
        }

        st_c = (st_c == 2) ? 0 : st_c + 1;
        st_i = (st_i == 2) ? 0 : st_i + 1;
    }

    if (!vmode) {
#pragma unroll
        for (int i = 0; i < 4; i++) {
#pragma unroll
            for (int j = 0; j < 4; j++) {
                const int row = bm + wm + i * 16 + gr;
                const int col = bn + wn + j * 8 + 2 * tg;
                const float2 b01 = *(const float2*)(bias + col);
                float2 o0, o1;
                o0.x = acc[i][j][0] + b01.x;
                o0.y = acc[i][j][1] + b01.y;
                o1.x = acc[i][j][2] + b01.x;
                o1.y = acc[i][j][3] + b01.y;
                *(float2*)(C + (size_t)row * DIM + col)       = o0;
                *(float2*)(C + (size_t)(row + 8) * DIM + col) = o1;
            }
        }
    } else {
        // fp16 transposed store: Vt[(b*16+h)*64+hd][keyperm16]
#pragma unroll
        for (int i = 0; i < 4; i++) {
#pragma unroll
            for (int j = 0; j < 4; j++) {
                const int row = bm + wm + i * 16 + gr;     // token (key)
                const int col = bn + wn + j * 8 + 2 * tg;  // hd global
                const float2 b01 = *(const float2*)(bias + col);
                const int bb  = row >> 11;
                const int tok = row & 2047;
                const int pt  = (tok & ~15) | vperm16(tok & 15);
                const int h   = col >> 6;
                const int hd  = col & 63;
                __half* vb = vtout
                    + (((size_t)bb * NHEAD + h) * 64 + hd) * SEQ;
                vb[pt]           = __float2half_rn(acc[i][j][0] + b01.x);
                vb[SEQ + pt]     = __float2half_rn(acc[i][j][1] + b01.y);
                vb[pt + 2]       = __float2half_rn(acc[i][j][2] + b01.x);
                vb[SEQ + pt + 2] = __float2half_rn(acc[i][j][3] + b01.y);
            }
        }
    }
}

__global__ __launch_bounds__(128, 4) void gemm_s4_kernel(
    const uint32_t* __restrict__ A, const uint32_t* __restrict__ W,
    const float* __restrict__ bias, float* __restrict__ C)
{
    extern __shared__ uint32_t gsm[];
    gemm_s4_body(A, W, bias, C, nullptr, 0, blockIdx.x, blockIdx.y, gsm);
}

__global__ __launch_bounds__(128, 4) void gemm_s4_qkv_kernel(
    const uint32_t* __restrict__ A, const uint32_t* __restrict__ Wp,
    const float* __restrict__ bq, const float* __restrict__ bk,
    const float* __restrict__ bv,
    float* __restrict__ Cq, float* __restrict__ Ck,
    __half* __restrict__ vt)
{
    extern __shared__ uint32_t gsm[];
    const float* b; float* C; int vmode;
    if (blockIdx.z == 0)      { b = bq; C = Cq;      vmode = 0; }
    else if (blockIdx.z == 1) { b = bk; C = Ck;      vmode = 0; }
    else                      { b = bv; C = nullptr; vmode = 1; }
    gemm_s4_body(A, Wp + (size_t)blockIdx.z * DIM * DIM, b, C, vt, vmode,
                 blockIdx.x, blockIdx.y, gsm);
}

// ---------------------------------------------------------------------------
// Prepack Q/K: fused RMSNorm + tf32 + head split + hd-perm (no key perm).
// ---------------------------------------------------------------------------
__global__ __launch_bounds__(128) void prepack_qk_kernel(
    const float* __restrict__ qin, const float* __restrict__ kin,
    const float* __restrict__ nqw, const float* __restrict__ nkw,
    uint32_t* __restrict__ qp, uint32_t* __restrict__ kp)
{
    const int row = blockIdx.x;
    const int isk = blockIdx.y;
    const float* src = (isk ? kin : qin) + (size_t)row * DIM;
    const float* w   = isk ? nkw : nqw;
    uint32_t* dstbuf = isk ? kp : qp;
    const int t = threadIdx.x;

    const float4 v0 = *(const float4*)(src + t * 8);
    const float4 v1 = *(const float4*)(src + t * 8 + 4);
    float ss = v0.x * v0.x + v0.y * v0.y + v0.z * v0.z + v0.w * v0.w
             + v1.x * v1.x + v1.y * v1.y + v1.z * v1.z + v1.w * v1.w;
#pragma unroll
    for (int off = 16; off > 0; off >>= 1)
        ss += __shfl_xor_sync(0xFFFFFFFFu, ss, off);
    __shared__ float red[4];
    if ((t & 31) == 0) red[t >> 5] = ss;
    __syncthreads();
    const float total = red[0] + red[1] + red[2] + red[3];

    const float SCALE = 0.125f * 1.4426950408889634f;
    float norm = rsqrtf(total * (1.0f / DIM) + 1e-6f);
    if (!isk) norm *= SCALE;

    const int b = row >> 11;
    const int s = row & 2047;
    const int h = t >> 3;
    const float4 w0 = *(const float4*)(w + t * 8);
    const float4 w1 = *(const float4*)(w + t * 8 + 4);

    const float y0 = v0.x * norm * w0.x, y1 = v0.y * norm * w0.y;
    const float y2 = v0.z * norm * w0.z, y3 = v0.w * norm * w0.w;
    const float y4 = v1.x * norm * w1.x, y5 = v1.y * norm * w1.y;
    const float y6 = v1.z * norm * w1.z, y7 = v1.w * norm * w1.w;

    uint32_t* dst = dstbuf + (((size_t)b * NHEAD + h) * SEQ + s) * 64
                  + (t & 7) * 8;
    uint4 o0, o1;
    o0.x = f2tf32(y0); o0.y = f2tf32(y4);
    o0.z = f2tf32(y1); o0.w = f2tf32(y5);
    o1.x = f2tf32(y2); o1.y = f2tf32(y6);
    o1.z = f2tf32(y3); o1.w = f2tf32(y7);
    *(uint4*)(dst)     = o0;
    *(uint4*)(dst + 4) = o1;
}

// ---------------------------------------------------------------------------
// Tensor-core flash attention v9: tf32 S-phase + fp16 PV phase (m16n8k16).
//  - fp16 rounding precision == tf32 (10 mantissa bits): rel_err preserved
//  - SMAX 12: p_max ~ 2^-3, fully fp16-normal range
//  - unpermuted key rows: S-accum pairs ARE the fp16 A-fragment pairs
//  - V in fp16 [hd][keyperm16]: one LDS.64 per (nt,j) = both B regs
//  - K-prefetch pipeline (R15), static-max softmax, packed tf32 epilogue.
// ---------------------------------------------------------------------------
#define ASTR 72
#define VSTR 40
#define SMAX 12.0f

__global__ __launch_bounds__(128, 4) void attn_tc_kernel(
    const uint32_t* __restrict__ qp, const uint32_t* __restrict__ kp,
    const __half* __restrict__ vt, uint32_t* __restrict__ outp)
{
    extern __shared__ uint32_t sm[];
    uint32_t* Qs = sm;                 // [64][ASTR]
    uint32_t* Ks = sm + 64 * ASTR;     // [64][ASTR]
    uint32_t* Vs = sm + 128 * ASTR;    // [64][VSTR]  (fp16 pairs)

    const int tid  = threadIdx.x;
    const int warp = tid >> 5;
    const int lane = tid & 31;
    const int gr   = lane >> 2;
    const int tg   = lane & 3;
    const int h    = blockIdx.y;
    const int b    = blockIdx.z;

    const int qrow0 = blockIdx.x * 64;
    const size_t bh = (size_t)b * NHEAD + h;
    const uint32_t* qbase = qp + (bh * SEQ + qrow0) * 64;

    const uint32_t qs_a = (uint32_t)__cvta_generic_to_shared(Qs);
    const uint32_t ks_a = (uint32_t)__cvta_generic_to_shared(Ks);
    const uint32_t vs_a = (uint32_t)__cvta_generic_to_shared(Vs);

    // K loader
    const int rr = tid >> 4;
    const int cc = (tid & 15) * 4;
    const uint32_t ksd = ks_a + (rr * ASTR + cc) * 4;
    const uint32_t* kg = kp + bh * SEQ * 64 + rr * 64 + cc;
    // V loader: vr = hd row base, vc = 16B chunk (8 fp16)
    const int vr = tid >> 3;
    const int vc = tid & 7;
    const uint32_t vsd = vs_a + (vr * VSTR + vc * 4) * 4;
    const __half* vg = vt + (bh * 64 + vr) * SEQ + vc * 8;

    // prologue group: Q (64 rows) + K(0)
#pragma unroll
    for (int n = 0; n < 8; n++)
        cp_async16(qs_a + ((rr + 8 * n) * ASTR + cc) * 4,
                   qbase + (rr + 8 * n) * 64 + cc);
#pragma unroll
    for (int n = 0; n < 8; n++)
        cp_async16(ksd + n * (8 * ASTR * 4), kg + n * (8 * 64));
    cp_commit();
    kg += 64 * 64;

    const int qr = warp * 16 + gr;

    float of[8][4];
#pragma unroll
    for (int nt = 0; nt < 8; nt++)
#pragma unroll
        for (int c = 0; c < 4; c++) of[nt][c] = 0.f;

    float l0 = 0.f, l1 = 0.f;

    for (int k0 = 0; k0 < SEQ; k0 += 64) {
        __syncthreads();   // PV(t-1) readers done (V buffer free)

        // issue V(t): 64 hd rows x 4 chunks of 16B (fp16)
#pragma unroll
        for (int n = 0; n < 4; n++)
            cp_async16(vsd + n * (16 * VSTR * 4),
                       vg + (size_t)n * 16 * SEQ + k0);
        cp_commit();

        // K(t) done (V(t) may still be in flight)
        asm volatile("cp.async.wait_group 1;\n" ::: "memory");
        __syncthreads();

        // S = Q @ K^T (tf32) — V(t) streams in underneath
        float sacc[8][4];
#pragma unroll
        for (int nt = 0; nt < 8; nt++)
#pragma unroll
            for (int c = 0; c < 4; c++) sacc[nt][c] = 0.f;

#pragma unroll
        for (int j = 0; j < 8; j++) {
            const uint2 q0 = *(const uint2*)&Qs[qr * ASTR + 8 * j + 2 * tg];
            const uint2 q1 = *(const uint2*)&Qs[(qr + 8) * ASTR + 8 * j + 2 * tg];
            uint32_t a[4] = {q0.x, q1.x, q0.y, q1.y};
#pragma unroll
            for (int nt = 0; nt < 8; nt++) {
                const uint2 kb = *(const uint2*)&Ks[(8 * nt + gr) * ASTR + 8 * j + 2 * tg];
                mma_tf32(sacc[nt], a, (const uint32_t*)&kb, sacc[nt]);
            }
        }

        // V(t) ready; all warps past S -> K buffer free for K(t+1)
        asm volatile("cp.async.wait_group 0;\n" ::: "memory");
        __syncthreads();

        if (k0 + 64 < SEQ) {
#pragma unroll
            for (int n = 0; n < 8; n++)
                cp_async16(ksd + n * (8 * ASTR * 4), kg + n * (8 * 64));
            cp_commit();
            kg += 64 * 64;
        }

        // fp16 PV: P = exp2(S - SMAX); O += P @ V  (16 keys per j-step)
#pragma unroll
        for (int j = 0; j < 4; j++) {
            const float p00 = ex2(sacc[2 * j][0] - SMAX);
            const float p01 = ex2(sacc[2 * j][1] - SMAX);
            const float p02 = ex2(sacc[2 * j][2] - SMAX);
            const float p03 = ex2(sacc[2 * j][3] - SMAX);
            const float p10 = ex2(sacc[2 * j + 1][0] - SMAX);
            const float p11 = ex2(sacc[2 * j + 1][1] - SMAX);
            const float p12 = ex2(sacc[2 * j + 1][2] - SMAX);
            const float p13 = ex2(sacc[2 * j + 1][3] - SMAX);
            uint32_t a[4];
            a[0] = pk_f16x2(p01, p00);   // row gr,   keys 2tg,2tg+1
            a[1] = pk_f16x2(p03, p02);   // row gr+8, keys 2tg,2tg+1
            a[2] = pk_f16x2(p11, p10);   // row gr,   keys 2tg+8,2tg+9
            a[3] = pk_f16x2(p13, p12);   // row gr+8, keys 2tg+8,2tg+9
            l0 += (p00 + p01) + (p10 + p11);
            l1 += (p02 + p03) + (p12 + p13);
#pragma unroll
            for (int nt = 0; nt < 8; nt++) {
                const uint2 vb = *(const uint2*)&Vs[(8 * nt + gr) * VSTR + 8 * j + 2 * tg];
                mma_f16(of[nt], a, (const uint32_t*)&vb, of[nt]);
            }
        }
    }

    l0 += __shfl_xor_sync(0xFFFFFFFFu, l0, 1);
    l0 += __shfl_xor_sync(0xFFFFFFFFu, l0, 2);
    l1 += __shfl_xor_sync(0xFFFFFFFFu, l1, 1);
    l1 += __shfl_xor_sync(0xFFFFFFFFu, l1, 2);
    const float inv0 = 1.f / l0;
    const float inv1 = 1.f / l1;

    const int pe = perm8(2 * tg);
    const int po = perm8(2 * tg + 1);
    uint32_t* o0 = outp + ((size_t)b * SEQ + qrow0 + qr) * DIM + h * HDIM;
    uint32_t* o1 = o0 + 8 * DIM;
#pragma unroll
    for (int nt = 0; nt < 8; nt++) {
        o0[8 * nt + pe] = f2tf32(of[nt][0] * inv0);
        o0[8 * nt + po] = f2tf32(of[nt][1] * inv0);
        o1[8 * nt + pe] = f2tf32(of[nt][2] * inv1);
        o1[8 * nt + po] = f2tf32(of[nt][3] * inv1);
    }
}

// ---------------------------------------------------------------------------
// Launch
// ---------------------------------------------------------------------------
extern "C" void kernel_launch(void* const* d_in, const int* in_sizes, int n_in,
                              void* d_out, int out_size)
{
    const float* x   = (const float*)d_in[0];
    const float* Wq  = (const float*)d_in[1];
    const float* bq  = (const float*)d_in[2];
    const float* Wk  = (const float*)d_in[3];
    const float* bk  = (const float*)d_in[4];
    const float* Wv  = (const float*)d_in[5];
    const float* bv  = (const float*)d_in[6];
    const float* Wo  = (const float*)d_in[7];
    const float* bo  = (const float*)d_in[8];
    const float* nqw = (const float*)d_in[9];
    const float* nkw = (const float*)d_in[10];
    float* out = (float*)d_out;

    float *dq, *dk;
    uint32_t *dqp, *dkp, *dxp, *dwp, *dap;
    __half* dvt;
    cudaGetSymbolAddress((void**)&dq,  g_q);
    cudaGetSymbolAddress((void**)&dk,  g_k);
    cudaGetSymbolAddress((void**)&dqp, g_qp);
    cudaGetSymbolAddress((void**)&dkp, g_kp);
    cudaGetSymbolAddress((void**)&dvt, g_vt);
    cudaGetSymbolAddress((void**)&dxp, g_xp);
    cudaGetSymbolAddress((void**)&dwp, g_wp);
    cudaGetSymbolAddress((void**)&dap, g_ap);

    const int gemm_smem = 3 * 192 * G2STR * 4;      // 55296 bytes
    cudaFuncSetAttribute(gemm_s4_kernel,
                         cudaFuncAttributeMaxDynamicSharedMemorySize, gemm_smem);
    cudaFuncSetAttribute(gemm_s4_qkv_kernel,
                         cudaFuncAttributeMaxDynamicSharedMemorySize, gemm_smem);
    const int attn_smem = (128 * ASTR + 64 * VSTR) * 4;   // 47104 bytes
    cudaFuncSetAttribute(attn_tc_kernel,
                         cudaFuncAttributeMaxDynamicSharedMemorySize, attn_smem);

    pack_all_kernel<<<MROWS / 2 + 2 * DIM, 256>>>(x, Wq, Wk, Wv, Wo, dxp, dwp);

    dim3 qkvgrid(DIM / 64, MROWS / 128, 3);   // (16, 32, 3)
    gemm_s4_qkv_kernel<<<qkvgrid, 128, gemm_smem>>>(
        dxp, dwp, bq, bk, bv, dq, dk, dvt);

    dim3 pgrid(MROWS, 2);
    prepack_qk_kernel<<<pgrid, 128>>>(dq, dk, nqw, nkw, dqp, dkp);

    dim3 agrid(SEQ / 64, NHEAD, BATCH);
    attn_tc_kernel<<<agrid, 128, attn_smem>>>(dqp, dkp, dvt, dap);

    dim3 ggrid(DIM / 64, MROWS / 128);        // (16, 32)
    gemm_s4_kernel<<<ggrid, 128, gemm_smem>>>(
        dap, dwp + 3 * (size_t)DIM * DIM, bo, out);
}